// round 3
// baseline (speedup 1.0000x reference)
#include <cuda_runtime.h>
#include <math.h>

// Problem constants
#define NMAX   50000
#define EMAX   800000
#define HEADS  4
#define HID    64
#define QK     256        // HEADS*HID
#define OCT    832        // 3*QK + HID
#define NGRAPH 64
#define GDIM   256
#define NCLS   10

// ---------------- scratch (device globals; no runtime allocation) ----------------
__device__ __align__(16) float    g_q   [NMAX * QK];
__device__ __align__(16) float    g_k   [NMAX * QK];
__device__ __align__(16) float    g_v   [NMAX * QK];
__device__ __align__(16) float    g_skip[NMAX * HID];
__device__ __align__(16) float    g_agg [NMAX * HID];   // head-mean folded
__device__ __align__(16) float    g_h1  [NMAX * HID];
__device__ __align__(16) float    g_h2  [NMAX * HID];
__device__ __align__(16) float    g_sew [EMAX * HEADS];
__device__ __align__(16) float    g_z   [NMAX * HEADS];
__device__ __align__(16) float    g_Wc  [128 * OCT];
__device__ __align__(16) float    g_bc  [OCT];
__device__ __align__(16) float    g_gsum[NGRAPH * HID];
__device__ __align__(16) float    g_gcnt[NGRAPH];

// ---------------- helpers ----------------
__device__ __forceinline__ void red_add_v4(float* p, float a, float b, float c, float d) {
    asm volatile("red.global.add.v4.f32 [%0], {%1,%2,%3,%4};"
                 :: "l"(p), "f"(a), "f"(b), "f"(c), "f"(d) : "memory");
}
__device__ __forceinline__ void ffma2(unsigned long long& d,
                                      unsigned long long a, unsigned long long b) {
    asm("fma.rn.f32x2 %0, %1, %2, %0;" : "+l"(d) : "l"(a), "l"(b));
}
__device__ __forceinline__ unsigned long long dup2(float v) {
    unsigned long long r;
    asm("mov.b64 %0, {%1, %1};" : "=l"(r) : "r"(__float_as_uint(v)));
    return r;
}
__device__ __forceinline__ float lo2(unsigned long long v) { return __uint_as_float((unsigned)v); }
__device__ __forceinline__ float hi2(unsigned long long v) { return __uint_as_float((unsigned)(v >> 32)); }

// ---------------- weight pack: Wc[K][832] = [Wq|Wk|Wv|Ws], bc[832] ----------------
__global__ void pack_w(const float* __restrict__ Wq, const float* __restrict__ bq,
                       const float* __restrict__ Wk, const float* __restrict__ bk,
                       const float* __restrict__ Wv, const float* __restrict__ bv,
                       const float* __restrict__ Ws, const float* __restrict__ bs, int K) {
    int idx = blockIdx.x * blockDim.x + threadIdx.x;
    int tot = K * OCT;
    if (idx < tot) {
        int k = idx / OCT, j = idx - k * OCT;
        float v;
        if      (j < 256) v = Wq[k * 256 + j];
        else if (j < 512) v = Wk[k * 256 + (j - 256)];
        else if (j < 768) v = Wv[k * 256 + (j - 512)];
        else              v = Ws[k * 64  + (j - 768)];
        g_Wc[idx] = v;
    }
    if (idx < OCT) {
        float b;
        if      (idx < 256) b = bq[idx];
        else if (idx < 512) b = bk[idx - 256];
        else if (idx < 768) b = bv[idx - 512];
        else                b = bs[idx - 768];
        g_bc[idx] = b;
    }
}

// ---------------- GEMM: C[N,832] = A[N,K] @ Wc[K,832] + bc ; routed to q/k/v/skip ----
// BM=128, BN=64, BK=16, 256 threads, 4x8 micro-tile with packed f32x2 FMA.
// A kept row-major in smem (scalar broadcast reads); B read as ulonglong2 pairs.
#define APAD 20
__global__ void gemm_qkvs(const float* __restrict__ A, int N, int K) {
    __shared__ float As[128 * APAD];   // [m][k] padded
    __shared__ float Bs[16 * 64];      // [k][n]
    int t  = threadIdx.x;
    int tx = t & 7, ty = t >> 3;       // tx: 8 col-groups, ty: 32 row-groups
    int row0 = blockIdx.x * 128, col0 = blockIdx.y * 64;
    unsigned long long acc[4][4];
    #pragma unroll
    for (int i = 0; i < 4; i++)
        #pragma unroll
        for (int j = 0; j < 4; j++) acc[i][j] = 0ull;

    for (int k0 = 0; k0 < K; k0 += 16) {
        #pragma unroll
        for (int ii = 0; ii < 2; ii++) {          // A: 128x16 = 512 float4, 2/thread
            int idx = t + ii * 256;
            int r = idx >> 2, cg = (idx & 3) << 2;
            int gr = row0 + r;
            float4 a = (gr < N) ? *(const float4*)&A[(size_t)gr * K + k0 + cg]
                                : make_float4(0.f, 0.f, 0.f, 0.f);
            *(float4*)&As[r * APAD + cg] = a;
        }
        {                                          // B: 16x64 = 256 float4, 1/thread
            int kk = t >> 4, j = (t & 15) << 2;
            *(float4*)&Bs[kk * 64 + j] = *(const float4*)&g_Wc[(size_t)(k0 + kk) * OCT + col0 + j];
        }
        __syncthreads();
        #pragma unroll
        for (int kk = 0; kk < 16; kk++) {
            ulonglong2 b0 = *(const ulonglong2*)&Bs[kk * 64 + tx * 8];
            ulonglong2 b1 = *(const ulonglong2*)&Bs[kk * 64 + tx * 8 + 4];
            #pragma unroll
            for (int i = 0; i < 4; i++) {
                unsigned long long a2 = dup2(As[(ty * 4 + i) * APAD + kk]);
                ffma2(acc[i][0], a2, b0.x);
                ffma2(acc[i][1], a2, b0.y);
                ffma2(acc[i][2], a2, b1.x);
                ffma2(acc[i][3], a2, b1.y);
            }
        }
        __syncthreads();
    }

    // epilogue: whole 64-col block lives in exactly one segment
    int y = blockIdx.y;
    float* dstbuf; int cbase; int rowstride;
    if      (y < 4)  { dstbuf = g_q;    cbase = col0;       rowstride = 256; }
    else if (y < 8)  { dstbuf = g_k;    cbase = col0 - 256; rowstride = 256; }
    else if (y < 12) { dstbuf = g_v;    cbase = col0 - 512; rowstride = 256; }
    else             { dstbuf = g_skip; cbase = 0;          rowstride = 64;  }

    float bias[8];
    #pragma unroll
    for (int j = 0; j < 8; j++) bias[j] = g_bc[col0 + tx * 8 + j];

    #pragma unroll
    for (int i = 0; i < 4; i++) {
        int n = row0 + ty * 4 + i;
        if (n >= N) continue;
        float o[8];
        #pragma unroll
        for (int jp = 0; jp < 4; jp++) {
            o[jp * 2 + 0] = lo2(acc[i][jp]) + bias[jp * 2 + 0];
            o[jp * 2 + 1] = hi2(acc[i][jp]) + bias[jp * 2 + 1];
        }
        float* p = &dstbuf[(size_t)n * rowstride + cbase + tx * 8];
        *(float4*)p       = make_float4(o[0], o[1], o[2], o[3]);
        *(float4*)(p + 4) = make_float4(o[4], o[5], o[6], o[7]);
    }
}

// ---------------- fused pass1: logits + exp + segment-sum z (warp per edge) ----------
// softmax is shift-invariant and logits are O(1): skip the segment-max entirely.
__global__ void edge_logits_exp(const int* __restrict__ ei, int E) {
    int w    = (blockIdx.x * blockDim.x + threadIdx.x) >> 5;
    int lane = threadIdx.x & 31;
    if (w >= E) return;
    int src = ei[w], dst = ei[E + w];
    const float4* qd = (const float4*)&g_q[(size_t)dst * QK];
    const float4* ks = (const float4*)&g_k[(size_t)src * QK];
    float ev[2];
    #pragma unroll
    for (int it = 0; it < 2; it++) {
        int idx = it * 32 + lane;
        float4 a = qd[idx], b = ks[idx];
        float p = a.x * b.x + a.y * b.y + a.z * b.z + a.w * b.w;
        p += __shfl_xor_sync(0xffffffffu, p, 1);
        p += __shfl_xor_sync(0xffffffffu, p, 2);
        p += __shfl_xor_sync(0xffffffffu, p, 4);
        p += __shfl_xor_sync(0xffffffffu, p, 8);
        ev[it] = __expf(p * 0.125f);     // 1/sqrt(64)
    }
    float y0 = __shfl_sync(0xffffffffu, ev[0], 16);
    float y1 = __shfl_sync(0xffffffffu, ev[1], 16);
    if (lane == 0) {
        // head order: h0=ev0@l0, h1=ev0@l16, h2=ev1@l0, h3=ev1@l16
        float4 e4 = make_float4(ev[0], y0, ev[1], y1);
        *(float4*)&g_sew[(size_t)w * 4] = e4;
        red_add_v4(&g_z[(size_t)dst * 4], e4.x, e4.y, e4.z, e4.w);
    }
}

// ---------------- pass3 (head-mean folded): agg64[dst] += sum_h (alpha_h/4)*v[src][h] ----
__global__ void edge_agg(const int* __restrict__ ei, int E) {
    int gid  = blockIdx.x * blockDim.x + threadIdx.x;
    int e    = gid >> 4;
    int l    = gid & 15;
    if (e >= E) return;
    int src = ei[e], dst = ei[E + e];
    float4 ev = *(const float4*)&g_sew[(size_t)e * 4];
    float4 zz = *(const float4*)&g_z[(size_t)dst * 4];
    float w0 = 0.25f * ev.x / zz.x;
    float w1 = 0.25f * ev.y / zz.y;
    float w2 = 0.25f * ev.z / zz.z;
    float w3 = 0.25f * ev.w / zz.w;
    const float* vb = &g_v[(size_t)src * QK + l * 4];
    float4 a = *(const float4*)(vb);
    float4 b = *(const float4*)(vb + 64);
    float4 c = *(const float4*)(vb + 128);
    float4 d = *(const float4*)(vb + 192);
    float o0 = w0 * a.x + w1 * b.x + w2 * c.x + w3 * d.x;
    float o1 = w0 * a.y + w1 * b.y + w2 * c.y + w3 * d.y;
    float o2 = w0 * a.z + w1 * b.z + w2 * c.z + w3 * d.z;
    float o3 = w0 * a.w + w1 * b.w + w2 * c.w + w3 * d.w;
    red_add_v4(&g_agg[(size_t)dst * HID + l * 4], o0, o1, o2, o3);
}

// ---------------- finalize: relu(agg + skip) ----------------
__global__ void finalize_conv(float* __restrict__ out, int N) {
    int idx = blockIdx.x * blockDim.x + threadIdx.x;   // over N*16 float4s
    if (idx >= N * (HID / 4)) return;
    float4 ag = *(const float4*)&g_agg[(size_t)idx * 4];
    float4 sk = *(const float4*)&g_skip[(size_t)idx * 4];
    float4 o;
    o.x = fmaxf(ag.x + sk.x, 0.f);
    o.y = fmaxf(ag.y + sk.y, 0.f);
    o.z = fmaxf(ag.z + sk.z, 0.f);
    o.w = fmaxf(ag.w + sk.w, 0.f);
    *(float4*)&out[(size_t)idx * 4] = o;
}

// ---------------- pool: per-graph mean of g_h2 (batch is sorted) ----------------
__global__ void pool_kernel(const int* __restrict__ batch, int N) {
    const int NPB = 256;
    int d = threadIdx.x;           // 0..63
    int n0 = blockIdx.x * NPB;
    int n1 = min(n0 + NPB, N);
    float acc = 0.f, cnt = 0.f;
    int cur = -1;
    for (int n = n0; n < n1; n++) {
        int g = batch[n];
        if (g != cur) {
            if (cur >= 0) {
                atomicAdd(&g_gsum[cur * HID + d], acc);
                if (d == 0) atomicAdd(&g_gcnt[cur], cnt);
            }
            cur = g; acc = 0.f; cnt = 0.f;
        }
        acc += g_h2[(size_t)n * HID + d];
        cnt += 1.f;
    }
    if (cur >= 0) {
        atomicAdd(&g_gsum[cur * HID + d], acc);
        if (d == 0) atomicAdd(&g_gcnt[cur], cnt);
    }
}

// ---------------- head: global MLP + concat + classifier (single block) ----------------
__global__ void head_kernel(const float* __restrict__ gf,
                            const float* __restrict__ gW1, const float* __restrict__ gb1,
                            const float* __restrict__ gW2, const float* __restrict__ gb2,
                            const float* __restrict__ hW1, const float* __restrict__ hb1,
                            const float* __restrict__ hW2, const float* __restrict__ hb2,
                            float* __restrict__ out) {
    __shared__ float sm_patch[NGRAPH * HID];
    __shared__ float sm_A[NGRAPH * HID];
    __shared__ float sm_B[NGRAPH * HID];
    int tid = threadIdx.x;

    for (int idx = tid; idx < NGRAPH * HID; idx += blockDim.x) {
        int g = idx >> 6;
        sm_patch[idx] = g_gsum[idx] / fmaxf(g_gcnt[g], 1.f);
    }
    __syncthreads();
    for (int idx = tid; idx < NGRAPH * HID; idx += blockDim.x) {
        int g = idx >> 6, j = idx & 63;
        float s = gb1[j];
        for (int k = 0; k < GDIM; k++) s += gf[g * GDIM + k] * gW1[k * HID + j];
        sm_A[idx] = fmaxf(s, 0.f);
    }
    __syncthreads();
    for (int idx = tid; idx < NGRAPH * HID; idx += blockDim.x) {
        int g = idx >> 6, j = idx & 63;
        float s = gb2[j];
        for (int k = 0; k < HID; k++) s += sm_A[g * HID + k] * gW2[k * HID + j];
        sm_B[idx] = fmaxf(s, 0.f);
    }
    __syncthreads();
    for (int idx = tid; idx < NGRAPH * HID; idx += blockDim.x) {
        int g = idx >> 6, j = idx & 63;
        float s = hb1[j];
        for (int k = 0; k < HID; k++) s += sm_patch[g * HID + k] * hW1[k * HID + j];
        for (int k = 0; k < HID; k++) s += sm_B[g * HID + k] * hW1[(HID + k) * HID + j];
        sm_A[idx] = fmaxf(s, 0.f);
    }
    __syncthreads();
    for (int idx = tid; idx < NGRAPH * NCLS; idx += blockDim.x) {
        int g = idx / NCLS, j = idx - g * NCLS;
        float s = hb2[j];
        for (int k = 0; k < HID; k++) s += sm_A[g * HID + k] * hW2[k * NCLS + j];
        out[idx] = s;
    }
}

// ---------------- host orchestration ----------------
static void run_conv(const float* xin, int K, int N, int E, const int* ei,
                     const float* Wq, const float* bq, const float* Wk, const float* bk,
                     const float* Wv, const float* bv, const float* Ws, const float* bs,
                     float* hout,
                     void* z_p, void* agg_p) {
    pack_w<<<(K * OCT + 255) / 256, 256>>>(Wq, bq, Wk, bk, Wv, bv, Ws, bs, K);
    cudaMemsetAsync(z_p,   0, (size_t)N * HEADS * sizeof(float), 0);
    cudaMemsetAsync(agg_p, 0, (size_t)N * HID * sizeof(float), 0);
    dim3 gg((N + 127) / 128, OCT / 64);
    gemm_qkvs<<<gg, 256>>>(xin, N, K);
    int lthreads = E * 32;
    edge_logits_exp<<<(lthreads + 255) / 256, 256>>>(ei, E);
    int athreads = E * 16;
    edge_agg<<<(athreads + 255) / 256, 256>>>(ei, E);
    finalize_conv<<<(N * (HID / 4) + 255) / 256, 256>>>(hout, N);
}

extern "C" void kernel_launch(void* const* d_in, const int* in_sizes, int n_in,
                              void* d_out, int out_size) {
    const float* x     = (const float*)d_in[0];
    const int*   ei    = (const int*)  d_in[1];
    const int*   batch = (const int*)  d_in[2];
    const float* gf    = (const float*)d_in[3];
    const float* c1[8]; for (int i = 0; i < 8; i++) c1[i] = (const float*)d_in[4 + i];
    const float* c2[8]; for (int i = 0; i < 8; i++) c2[i] = (const float*)d_in[12 + i];
    const float* gW1 = (const float*)d_in[20]; const float* gb1 = (const float*)d_in[21];
    const float* gW2 = (const float*)d_in[22]; const float* gb2 = (const float*)d_in[23];
    const float* hW1 = (const float*)d_in[24]; const float* hb1 = (const float*)d_in[25];
    const float* hW2 = (const float*)d_in[26]; const float* hb2 = (const float*)d_in[27];

    int N = in_sizes[0] / 128;
    int E = in_sizes[1] / 2;

    void *p_h1, *p_h2, *p_z, *p_agg, *p_gsum, *p_gcnt;
    cudaGetSymbolAddress(&p_h1,   g_h1);
    cudaGetSymbolAddress(&p_h2,   g_h2);
    cudaGetSymbolAddress(&p_z,    g_z);
    cudaGetSymbolAddress(&p_agg,  g_agg);
    cudaGetSymbolAddress(&p_gsum, g_gsum);
    cudaGetSymbolAddress(&p_gcnt, g_gcnt);

    // conv1 (in=128)
    run_conv(x, 128, N, E, ei,
             c1[0], c1[1], c1[2], c1[3], c1[4], c1[5], c1[6], c1[7],
             (float*)p_h1, p_z, p_agg);
    // conv2 (in=64)
    run_conv((const float*)p_h1, 64, N, E, ei,
             c2[0], c2[1], c2[2], c2[3], c2[4], c2[5], c2[6], c2[7],
             (float*)p_h2, p_z, p_agg);

    // pooling
    cudaMemsetAsync(p_gsum, 0, NGRAPH * HID * sizeof(float), 0);
    cudaMemsetAsync(p_gcnt, 0, NGRAPH * sizeof(float), 0);
    pool_kernel<<<(N + 255) / 256, HID>>>(batch, N);

    // head
    head_kernel<<<1, 256>>>(gf, gW1, gb1, gW2, gb2, hW1, hb1, hW2, hb2, (float*)d_out);
}

// round 4
// speedup vs baseline: 1.1039x; 1.1039x over previous
#include <cuda_runtime.h>
#include <math.h>

// Problem constants
#define NMAX   50000
#define EMAX   800000
#define HEADS  4
#define HID    64
#define QK     256        // HEADS*HID
#define OCT    832        // 3*QK + HID
#define NGRAPH 64
#define GDIM   256
#define NCLS   10

// ---------------- scratch (device globals; no runtime allocation) ----------------
__device__ __align__(16) float    g_q   [NMAX * QK];
__device__ __align__(16) float    g_k   [NMAX * QK];
__device__ __align__(16) float    g_v   [NMAX * QK];
__device__ __align__(16) float    g_skip[NMAX * HID];
__device__ __align__(16) float    g_agg [NMAX * HID];   // head-mean folded
__device__ __align__(16) float    g_h1  [NMAX * HID];
__device__ __align__(16) float    g_h2  [NMAX * HID];
__device__ __align__(16) float    g_sew [EMAX * HEADS];
__device__ __align__(16) float    g_z   [NMAX * HEADS];
__device__ __align__(16) float    g_Wc  [128 * OCT];
__device__ __align__(16) float    g_bc  [OCT];
__device__ __align__(16) float    g_gsum[NGRAPH * HID];
__device__ __align__(16) float    g_gcnt[NGRAPH];

// ---------------- helpers ----------------
__device__ __forceinline__ void red_add_v4(float* p, float a, float b, float c, float d) {
    asm volatile("red.global.add.v4.f32 [%0], {%1,%2,%3,%4};"
                 :: "l"(p), "f"(a), "f"(b), "f"(c), "f"(d) : "memory");
}
__device__ __forceinline__ unsigned f2u(float f) { return __float_as_uint(f); }

// split fp32 into tf32 hi + tf32 lo (3xTF32 trick)
__device__ __forceinline__ void tf32_split(float v, float& hf, float& lf) {
    unsigned h;
    asm("cvt.rna.tf32.f32 %0, %1;" : "=r"(h) : "f"(v));
    hf = __uint_as_float(h);
    float r = v - hf;
    unsigned l;
    asm("cvt.rna.tf32.f32 %0, %1;" : "=r"(l) : "f"(r));
    lf = __uint_as_float(l);
}

#define MMA_TF32(c, a, b)                                                     \
    asm volatile("mma.sync.aligned.m16n8k8.row.col.f32.tf32.tf32.f32 "        \
                 "{%0,%1,%2,%3}, {%4,%5,%6,%7}, {%8,%9}, {%0,%1,%2,%3};"      \
                 : "+f"((c)[0]), "+f"((c)[1]), "+f"((c)[2]), "+f"((c)[3])     \
                 : "r"((a)[0]), "r"((a)[1]), "r"((a)[2]), "r"((a)[3]),        \
                   "r"((b)[0]), "r"((b)[1]))

// ---------------- weight pack: Wc[K][832] = [Wq|Wk|Wv|Ws], bc[832] ----------------
__global__ void pack_w(const float* __restrict__ Wq, const float* __restrict__ bq,
                       const float* __restrict__ Wk, const float* __restrict__ bk,
                       const float* __restrict__ Wv, const float* __restrict__ bv,
                       const float* __restrict__ Ws, const float* __restrict__ bs, int K) {
    int idx = blockIdx.x * blockDim.x + threadIdx.x;
    int tot = K * OCT;
    if (idx < tot) {
        int k = idx / OCT, j = idx - k * OCT;
        float v;
        if      (j < 256) v = Wq[k * 256 + j];
        else if (j < 512) v = Wk[k * 256 + (j - 256)];
        else if (j < 768) v = Wv[k * 256 + (j - 512)];
        else              v = Ws[k * 64  + (j - 768)];
        g_Wc[idx] = v;
    }
    if (idx < OCT) {
        float b;
        if      (idx < 256) b = bq[idx];
        else if (idx < 512) b = bk[idx - 256];
        else if (idx < 768) b = bv[idx - 512];
        else                b = bs[idx - 768];
        g_bc[idx] = b;
    }
}

// ---------------- GEMM: C[N,832] = A[N,K] @ Wc[K,832] + bc ; routed to q/k/v/skip ----
// 3xTF32 tensor-core GEMM. BM=128, BN=64, BK=16, 256 threads (8 warps, 4x2 tile grid),
// 32x32 per warp via m16n8k8 fragments. hi/lo split done once at smem staging.
#define ASTR 132
#define BSTR 68
__global__ void __launch_bounds__(256, 2) gemm_qkvs(const float* __restrict__ A, int N, int K) {
    __shared__ float As[2][16 * ASTR];   // [hi/lo][k][m]
    __shared__ float Bs[2][16 * BSTR];   // [hi/lo][k][n]
    const int t    = threadIdx.x;
    const int lane = t & 31, wid = t >> 5;
    const int warp_m = wid & 3;          // 0..3 -> 32-row slab
    const int warp_n = wid >> 2;         // 0..1 -> 32-col slab
    const int row0 = blockIdx.x * 128, col0 = blockIdx.y * 64;
    const int lq = lane >> 2;            // 0..7
    const int lr = lane & 3;             // 0..3

    float c[2][4][4];
    #pragma unroll
    for (int mt = 0; mt < 2; mt++)
        #pragma unroll
        for (int nt = 0; nt < 4; nt++)
            #pragma unroll
            for (int i = 0; i < 4; i++) c[mt][nt][i] = 0.f;

    for (int k0 = 0; k0 < K; k0 += 16) {
        // --- stage A 128x16 -> As[k][m] (transposed), hi/lo split ---
        #pragma unroll
        for (int ii = 0; ii < 2; ii++) {
            int idx = t + ii * 256;
            int r = idx >> 2, cg = (idx & 3) << 2;
            int gr = row0 + r;
            float4 a = (gr < N) ? *(const float4*)&A[(size_t)gr * K + k0 + cg]
                                : make_float4(0.f, 0.f, 0.f, 0.f);
            float v[4] = {a.x, a.y, a.z, a.w};
            #pragma unroll
            for (int j = 0; j < 4; j++) {
                float hf, lf; tf32_split(v[j], hf, lf);
                As[0][(cg + j) * ASTR + r] = hf;
                As[1][(cg + j) * ASTR + r] = lf;
            }
        }
        // --- stage B 16x64 -> Bs[k][n], hi/lo split ---
        {
            int kk = t >> 4, j = (t & 15) << 2;
            float4 b = *(const float4*)&g_Wc[(size_t)(k0 + kk) * OCT + col0 + j];
            float v[4] = {b.x, b.y, b.z, b.w};
            #pragma unroll
            for (int j4 = 0; j4 < 4; j4++) {
                float hf, lf; tf32_split(v[j4], hf, lf);
                Bs[0][kk * BSTR + j + j4] = hf;
                Bs[1][kk * BSTR + j + j4] = lf;
            }
        }
        __syncthreads();

        #pragma unroll
        for (int k8 = 0; k8 < 16; k8 += 8) {
            int kq = k8 + lr;
            unsigned ah[2][4], al[2][4];
            #pragma unroll
            for (int mt = 0; mt < 2; mt++) {
                int r0 = warp_m * 32 + mt * 16 + lq;
                ah[mt][0] = f2u(As[0][kq * ASTR + r0]);
                ah[mt][1] = f2u(As[0][kq * ASTR + r0 + 8]);
                ah[mt][2] = f2u(As[0][(kq + 4) * ASTR + r0]);
                ah[mt][3] = f2u(As[0][(kq + 4) * ASTR + r0 + 8]);
                al[mt][0] = f2u(As[1][kq * ASTR + r0]);
                al[mt][1] = f2u(As[1][kq * ASTR + r0 + 8]);
                al[mt][2] = f2u(As[1][(kq + 4) * ASTR + r0]);
                al[mt][3] = f2u(As[1][(kq + 4) * ASTR + r0 + 8]);
            }
            unsigned bh[4][2], bl[4][2];
            #pragma unroll
            for (int nt = 0; nt < 4; nt++) {
                int n = warp_n * 32 + nt * 8 + lq;
                bh[nt][0] = f2u(Bs[0][kq * BSTR + n]);
                bh[nt][1] = f2u(Bs[0][(kq + 4) * BSTR + n]);
                bl[nt][0] = f2u(Bs[1][kq * BSTR + n]);
                bl[nt][1] = f2u(Bs[1][(kq + 4) * BSTR + n]);
            }
            #pragma unroll
            for (int mt = 0; mt < 2; mt++)
                #pragma unroll
                for (int nt = 0; nt < 4; nt++) {
                    MMA_TF32(c[mt][nt], ah[mt], bh[nt]);
                    MMA_TF32(c[mt][nt], al[mt], bh[nt]);
                    MMA_TF32(c[mt][nt], ah[mt], bl[nt]);
                }
        }
        __syncthreads();
    }

    // --- epilogue: whole 64-col block lives in exactly one segment ---
    int y = blockIdx.y;
    float* dstbuf; int segoff; int rowstride;
    if      (y < 4)  { dstbuf = g_q;    segoff = col0;       rowstride = 256; }
    else if (y < 8)  { dstbuf = g_k;    segoff = col0 - 256; rowstride = 256; }
    else if (y < 12) { dstbuf = g_v;    segoff = col0 - 512; rowstride = 256; }
    else             { dstbuf = g_skip; segoff = 0;          rowstride = 64;  }

    #pragma unroll
    for (int mt = 0; mt < 2; mt++) {
        int r = row0 + warp_m * 32 + mt * 16 + lq;
        #pragma unroll
        for (int nt = 0; nt < 4; nt++) {
            int jc_in = warp_n * 32 + nt * 8 + lr * 2;   // in-block col
            float b0 = g_bc[col0 + jc_in];
            float b1 = g_bc[col0 + jc_in + 1];
            if (r < N) {
                float2 o = make_float2(c[mt][nt][0] + b0, c[mt][nt][1] + b1);
                *(float2*)&dstbuf[(size_t)r * rowstride + segoff + jc_in] = o;
            }
            if (r + 8 < N) {
                float2 o = make_float2(c[mt][nt][2] + b0, c[mt][nt][3] + b1);
                *(float2*)&dstbuf[(size_t)(r + 8) * rowstride + segoff + jc_in] = o;
            }
        }
    }
}

// ---------------- fused pass1: logits + exp + segment-sum z (warp per edge) ----------
__global__ void edge_logits_exp(const int* __restrict__ ei, int E) {
    int w    = (blockIdx.x * blockDim.x + threadIdx.x) >> 5;
    int lane = threadIdx.x & 31;
    if (w >= E) return;
    int src = ei[w], dst = ei[E + w];
    const float4* qd = (const float4*)&g_q[(size_t)dst * QK];
    const float4* ks = (const float4*)&g_k[(size_t)src * QK];
    float ev[2];
    #pragma unroll
    for (int it = 0; it < 2; it++) {
        int idx = it * 32 + lane;
        float4 a = qd[idx], b = ks[idx];
        float p = a.x * b.x + a.y * b.y + a.z * b.z + a.w * b.w;
        p += __shfl_xor_sync(0xffffffffu, p, 1);
        p += __shfl_xor_sync(0xffffffffu, p, 2);
        p += __shfl_xor_sync(0xffffffffu, p, 4);
        p += __shfl_xor_sync(0xffffffffu, p, 8);
        ev[it] = __expf(p * 0.125f);     // 1/sqrt(64)
    }
    float y0 = __shfl_sync(0xffffffffu, ev[0], 16);
    float y1 = __shfl_sync(0xffffffffu, ev[1], 16);
    if (lane == 0) {
        float4 e4 = make_float4(ev[0], y0, ev[1], y1);
        *(float4*)&g_sew[(size_t)w * 4] = e4;
        red_add_v4(&g_z[(size_t)dst * 4], e4.x, e4.y, e4.z, e4.w);
    }
}

// ---------------- pass3 (head-mean folded): agg64[dst] += sum_h (alpha_h/4)*v[src][h] ----
__global__ void edge_agg(const int* __restrict__ ei, int E) {
    int gid  = blockIdx.x * blockDim.x + threadIdx.x;
    int e    = gid >> 4;
    int l    = gid & 15;
    if (e >= E) return;
    int src = ei[e], dst = ei[E + e];
    float4 ev = *(const float4*)&g_sew[(size_t)e * 4];
    float4 zz = *(const float4*)&g_z[(size_t)dst * 4];
    float w0 = 0.25f * ev.x / zz.x;
    float w1 = 0.25f * ev.y / zz.y;
    float w2 = 0.25f * ev.z / zz.z;
    float w3 = 0.25f * ev.w / zz.w;
    const float* vb = &g_v[(size_t)src * QK + l * 4];
    float4 a = *(const float4*)(vb);
    float4 b = *(const float4*)(vb + 64);
    float4 c = *(const float4*)(vb + 128);
    float4 d = *(const float4*)(vb + 192);
    float o0 = w0 * a.x + w1 * b.x + w2 * c.x + w3 * d.x;
    float o1 = w0 * a.y + w1 * b.y + w2 * c.y + w3 * d.y;
    float o2 = w0 * a.z + w1 * b.z + w2 * c.z + w3 * d.z;
    float o3 = w0 * a.w + w1 * b.w + w2 * c.w + w3 * d.w;
    red_add_v4(&g_agg[(size_t)dst * HID + l * 4], o0, o1, o2, o3);
}

// ---------------- finalize: relu(agg + skip) ----------------
__global__ void finalize_conv(float* __restrict__ out, int N) {
    int idx = blockIdx.x * blockDim.x + threadIdx.x;   // over N*16 float4s
    if (idx >= N * (HID / 4)) return;
    float4 ag = *(const float4*)&g_agg[(size_t)idx * 4];
    float4 sk = *(const float4*)&g_skip[(size_t)idx * 4];
    float4 o;
    o.x = fmaxf(ag.x + sk.x, 0.f);
    o.y = fmaxf(ag.y + sk.y, 0.f);
    o.z = fmaxf(ag.z + sk.z, 0.f);
    o.w = fmaxf(ag.w + sk.w, 0.f);
    *(float4*)&out[(size_t)idx * 4] = o;
}

// ---------------- pool: per-graph mean of g_h2 (batch is sorted) ----------------
__global__ void pool_kernel(const int* __restrict__ batch, int N) {
    const int NPB = 256;
    int d = threadIdx.x;           // 0..63
    int n0 = blockIdx.x * NPB;
    int n1 = min(n0 + NPB, N);
    float acc = 0.f, cnt = 0.f;
    int cur = -1;
    for (int n = n0; n < n1; n++) {
        int g = batch[n];
        if (g != cur) {
            if (cur >= 0) {
                atomicAdd(&g_gsum[cur * HID + d], acc);
                if (d == 0) atomicAdd(&g_gcnt[cur], cnt);
            }
            cur = g; acc = 0.f; cnt = 0.f;
        }
        acc += g_h2[(size_t)n * HID + d];
        cnt += 1.f;
    }
    if (cur >= 0) {
        atomicAdd(&g_gsum[cur * HID + d], acc);
        if (d == 0) atomicAdd(&g_gcnt[cur], cnt);
    }
}

// ---------------- head: global MLP + concat + classifier (single block) ----------------
__global__ void head_kernel(const float* __restrict__ gf,
                            const float* __restrict__ gW1, const float* __restrict__ gb1,
                            const float* __restrict__ gW2, const float* __restrict__ gb2,
                            const float* __restrict__ hW1, const float* __restrict__ hb1,
                            const float* __restrict__ hW2, const float* __restrict__ hb2,
                            float* __restrict__ out) {
    __shared__ float sm_patch[NGRAPH * HID];
    __shared__ float sm_A[NGRAPH * HID];
    __shared__ float sm_B[NGRAPH * HID];
    int tid = threadIdx.x;

    for (int idx = tid; idx < NGRAPH * HID; idx += blockDim.x) {
        int g = idx >> 6;
        sm_patch[idx] = g_gsum[idx] / fmaxf(g_gcnt[g], 1.f);
    }
    __syncthreads();
    for (int idx = tid; idx < NGRAPH * HID; idx += blockDim.x) {
        int g = idx >> 6, j = idx & 63;
        float s = gb1[j];
        for (int k = 0; k < GDIM; k++) s += gf[g * GDIM + k] * gW1[k * HID + j];
        sm_A[idx] = fmaxf(s, 0.f);
    }
    __syncthreads();
    for (int idx = tid; idx < NGRAPH * HID; idx += blockDim.x) {
        int g = idx >> 6, j = idx & 63;
        float s = gb2[j];
        for (int k = 0; k < HID; k++) s += sm_A[g * HID + k] * gW2[k * HID + j];
        sm_B[idx] = fmaxf(s, 0.f);
    }
    __syncthreads();
    for (int idx = tid; idx < NGRAPH * HID; idx += blockDim.x) {
        int g = idx >> 6, j = idx & 63;
        float s = hb1[j];
        for (int k = 0; k < HID; k++) s += sm_patch[g * HID + k] * hW1[k * HID + j];
        for (int k = 0; k < HID; k++) s += sm_B[g * HID + k] * hW1[(HID + k) * HID + j];
        sm_A[idx] = fmaxf(s, 0.f);
    }
    __syncthreads();
    for (int idx = tid; idx < NGRAPH * NCLS; idx += blockDim.x) {
        int g = idx / NCLS, j = idx - g * NCLS;
        float s = hb2[j];
        for (int k = 0; k < HID; k++) s += sm_A[g * HID + k] * hW2[k * NCLS + j];
        out[idx] = s;
    }
}

// ---------------- host orchestration ----------------
static void run_conv(const float* xin, int K, int N, int E, const int* ei,
                     const float* Wq, const float* bq, const float* Wk, const float* bk,
                     const float* Wv, const float* bv, const float* Ws, const float* bs,
                     float* hout,
                     void* z_p, void* agg_p) {
    pack_w<<<(K * OCT + 255) / 256, 256>>>(Wq, bq, Wk, bk, Wv, bv, Ws, bs, K);
    cudaMemsetAsync(z_p,   0, (size_t)N * HEADS * sizeof(float), 0);
    cudaMemsetAsync(agg_p, 0, (size_t)N * HID * sizeof(float), 0);
    dim3 gg((N + 127) / 128, OCT / 64);
    gemm_qkvs<<<gg, 256>>>(xin, N, K);
    int lthreads = E * 32;
    edge_logits_exp<<<(lthreads + 255) / 256, 256>>>(ei, E);
    int athreads = E * 16;
    edge_agg<<<(athreads + 255) / 256, 256>>>(ei, E);
    finalize_conv<<<(N * (HID / 4) + 255) / 256, 256>>>(hout, N);
}

extern "C" void kernel_launch(void* const* d_in, const int* in_sizes, int n_in,
                              void* d_out, int out_size) {
    const float* x     = (const float*)d_in[0];
    const int*   ei    = (const int*)  d_in[1];
    const int*   batch = (const int*)  d_in[2];
    const float* gf    = (const float*)d_in[3];
    const float* c1[8]; for (int i = 0; i < 8; i++) c1[i] = (const float*)d_in[4 + i];
    const float* c2[8]; for (int i = 0; i < 8; i++) c2[i] = (const float*)d_in[12 + i];
    const float* gW1 = (const float*)d_in[20]; const float* gb1 = (const float*)d_in[21];
    const float* gW2 = (const float*)d_in[22]; const float* gb2 = (const float*)d_in[23];
    const float* hW1 = (const float*)d_in[24]; const float* hb1 = (const float*)d_in[25];
    const float* hW2 = (const float*)d_in[26]; const float* hb2 = (const float*)d_in[27];

    int N = in_sizes[0] / 128;
    int E = in_sizes[1] / 2;

    void *p_h1, *p_h2, *p_z, *p_agg, *p_gsum, *p_gcnt;
    cudaGetSymbolAddress(&p_h1,   g_h1);
    cudaGetSymbolAddress(&p_h2,   g_h2);
    cudaGetSymbolAddress(&p_z,    g_z);
    cudaGetSymbolAddress(&p_agg,  g_agg);
    cudaGetSymbolAddress(&p_gsum, g_gsum);
    cudaGetSymbolAddress(&p_gcnt, g_gcnt);

    // conv1 (in=128)
    run_conv(x, 128, N, E, ei,
             c1[0], c1[1], c1[2], c1[3], c1[4], c1[5], c1[6], c1[7],
             (float*)p_h1, p_z, p_agg);
    // conv2 (in=64)
    run_conv((const float*)p_h1, 64, N, E, ei,
             c2[0], c2[1], c2[2], c2[3], c2[4], c2[5], c2[6], c2[7],
             (float*)p_h2, p_z, p_agg);

    // pooling
    cudaMemsetAsync(p_gsum, 0, NGRAPH * HID * sizeof(float), 0);
    cudaMemsetAsync(p_gcnt, 0, NGRAPH * sizeof(float), 0);
    pool_kernel<<<(N + 255) / 256, HID>>>(batch, N);

    // head
    head_kernel<<<1, 256>>>(gf, gW1, gb1, gW2, gb2, hW1, hb1, hW2, hb2, (float*)d_out);
}

// round 6
// speedup vs baseline: 1.2828x; 1.1620x over previous
#include <cuda_runtime.h>
#include <cuda_bf16.h>
#include <math.h>
#include <cstdint>

// Problem constants
#define NMAX   50000
#define EMAX   800000
#define HEADS  4
#define HID    64
#define QK     256        // HEADS*HID
#define OCT    832        // 3*QK + HID
#define NGRAPH 64
#define GDIM   256
#define NCLS   10

// ---------------- scratch (device globals; no runtime allocation) ----------------
__device__ __align__(16) float    g_q   [NMAX * QK];
__device__ __align__(16) float    g_k   [NMAX * QK];
__device__ __align__(16) float    g_v   [NMAX * QK];
__device__ __align__(16) float    g_skip[NMAX * HID];
__device__ __align__(16) float    g_agg [NMAX * HID];   // head-mean folded
__device__ __align__(16) float    g_h1  [NMAX * HID];
__device__ __align__(16) float    g_h2  [NMAX * HID];
__device__ __align__(16) float    g_sew [EMAX * HEADS];
__device__ __align__(16) float    g_z   [NMAX * HEADS];
__device__ __align__(16) float    g_Wc  [128 * OCT];
__device__ __align__(16) float    g_bc  [OCT];
__device__ __align__(16) float    g_gsum[NGRAPH * HID];
__device__ __align__(16) float    g_gcnt[NGRAPH];

// ---------------- helpers ----------------
__device__ __forceinline__ void red_add_v4(float* p, float a, float b, float c, float d) {
    asm volatile("red.global.add.v4.f32 [%0], {%1,%2,%3,%4};"
                 :: "l"(p), "f"(a), "f"(b), "f"(c), "f"(d) : "memory");
}
// pack two fp32 into one uint32 of two bf16 (lo half = first)
__device__ __forceinline__ uint32_t pack_bf16(float a, float b) {
    __nv_bfloat16 ha = __float2bfloat16_rn(a);
    __nv_bfloat16 hb = __float2bfloat16_rn(b);
    return (uint32_t)__bfloat16_as_ushort(ha) | ((uint32_t)__bfloat16_as_ushort(hb) << 16);
}
__device__ __forceinline__ float bf_hi_res(float v) {   // v - bf16(v)
    return v - __bfloat162float(__float2bfloat16_rn(v));
}

#define MMA_BF16(c, a, b)                                                     \
    asm volatile("mma.sync.aligned.m16n8k16.row.col.f32.bf16.bf16.f32 "       \
                 "{%0,%1,%2,%3}, {%4,%5,%6,%7}, {%8,%9}, {%0,%1,%2,%3};"      \
                 : "+f"((c)[0]), "+f"((c)[1]), "+f"((c)[2]), "+f"((c)[3])     \
                 : "r"((a)[0]), "r"((a)[1]), "r"((a)[2]), "r"((a)[3]),        \
                   "r"((b)[0]), "r"((b)[1]))

// ---------------- weight pack: Wc[K][832] = [Wq|Wk|Wv|Ws], bc[832] ----------------
__global__ void pack_w(const float* __restrict__ Wq, const float* __restrict__ bq,
                       const float* __restrict__ Wk, const float* __restrict__ bk,
                       const float* __restrict__ Wv, const float* __restrict__ bv,
                       const float* __restrict__ Ws, const float* __restrict__ bs, int K) {
    int idx = blockIdx.x * blockDim.x + threadIdx.x;
    int tot = K * OCT;
    if (idx < tot) {
        int k = idx / OCT, j = idx - k * OCT;
        float v;
        if      (j < 256) v = Wq[k * 256 + j];
        else if (j < 512) v = Wk[k * 256 + (j - 256)];
        else if (j < 768) v = Wv[k * 256 + (j - 512)];
        else              v = Ws[k * 64  + (j - 768)];
        g_Wc[idx] = v;
    }
    if (idx < OCT) {
        float b;
        if      (idx < 256) b = bq[idx];
        else if (idx < 512) b = bk[idx - 256];
        else if (idx < 768) b = bv[idx - 512];
        else                b = bs[idx - 768];
        g_bc[idx] = b;
    }
}

// ---------------- GEMM: C[N,832] = A[N,K] @ Wc[K,832] + bc ; routed to q/k/v/skip ----
// 3xBF16-split tensor-core GEMM via mma.sync.m16n8k16. BM=128, BN=64, BK=16,
// 256 threads (8 warps, 4x2 tile grid), 32x32 per warp. hi/lo split at smem staging.
// A staged as packed k-pair uint32 [kp][m] (stride 136), B as [kp][n] (stride 72).
#define ASTR32 136
#define BSTR32 72
__global__ void __launch_bounds__(256, 2) gemm_qkvs(const float* __restrict__ A, int N, int K) {
    __shared__ uint32_t As[2][8 * ASTR32];   // [hi/lo][kpair][m]
    __shared__ uint32_t Bs[2][8 * BSTR32];   // [hi/lo][kpair][n]
    const int t    = threadIdx.x;
    const int lane = t & 31, wid = t >> 5;
    const int warp_m = wid & 3;          // 0..3 -> 32-row slab
    const int warp_n = wid >> 2;         // 0..1 -> 32-col slab
    const int row0 = blockIdx.x * 128, col0 = blockIdx.y * 64;
    const int lq = lane >> 2;            // 0..7
    const int lr = lane & 3;             // 0..3

    float c[2][4][4];
    #pragma unroll
    for (int mt = 0; mt < 2; mt++)
        #pragma unroll
        for (int nt = 0; nt < 4; nt++)
            #pragma unroll
            for (int i = 0; i < 4; i++) c[mt][nt][i] = 0.f;

    for (int k0 = 0; k0 < K; k0 += 16) {
        // --- stage A 128x16 -> As[hi/lo][kp][m] packed k-pairs ---
        #pragma unroll
        for (int ii = 0; ii < 2; ii++) {
            int idx = t + ii * 256;
            int r = idx >> 2, cg = (idx & 3) << 2;   // cg in {0,4,8,12}
            int gr = row0 + r;
            float4 a = (gr < N) ? *(const float4*)&A[(size_t)gr * K + k0 + cg]
                                : make_float4(0.f, 0.f, 0.f, 0.f);
            int kp = cg >> 1;
            As[0][kp * ASTR32 + r]       = pack_bf16(a.x, a.y);
            As[0][(kp + 1) * ASTR32 + r] = pack_bf16(a.z, a.w);
            As[1][kp * ASTR32 + r]       = pack_bf16(bf_hi_res(a.x), bf_hi_res(a.y));
            As[1][(kp + 1) * ASTR32 + r] = pack_bf16(bf_hi_res(a.z), bf_hi_res(a.w));
        }
        // --- stage B 16x64 -> Bs[hi/lo][kp][n] packed over k ---
        if (t < 128) {
            int kp = t >> 4, j4 = (t & 15) << 2;
            const float* r0p = &g_Wc[(size_t)(k0 + 2 * kp) * OCT + col0 + j4];
            const float* r1p = r0p + OCT;
            float4 b0 = *(const float4*)r0p;
            float4 b1 = *(const float4*)r1p;
            float v0[4] = {b0.x, b0.y, b0.z, b0.w};
            float v1[4] = {b1.x, b1.y, b1.z, b1.w};
            #pragma unroll
            for (int i = 0; i < 4; i++) {
                Bs[0][kp * BSTR32 + j4 + i] = pack_bf16(v0[i], v1[i]);
                Bs[1][kp * BSTR32 + j4 + i] = pack_bf16(bf_hi_res(v0[i]), bf_hi_res(v1[i]));
            }
        }
        __syncthreads();

        // --- fragments + MMAs (one k16 step per tile) ---
        uint32_t ah[2][4], al[2][4];
        #pragma unroll
        for (int mt = 0; mt < 2; mt++) {
            int r0 = warp_m * 32 + mt * 16 + lq;
            ah[mt][0] = As[0][lr * ASTR32 + r0];
            ah[mt][1] = As[0][lr * ASTR32 + r0 + 8];
            ah[mt][2] = As[0][(lr + 4) * ASTR32 + r0];
            ah[mt][3] = As[0][(lr + 4) * ASTR32 + r0 + 8];
            al[mt][0] = As[1][lr * ASTR32 + r0];
            al[mt][1] = As[1][lr * ASTR32 + r0 + 8];
            al[mt][2] = As[1][(lr + 4) * ASTR32 + r0];
            al[mt][3] = As[1][(lr + 4) * ASTR32 + r0 + 8];
        }
        uint32_t bh[4][2], bl[4][2];
        #pragma unroll
        for (int nt = 0; nt < 4; nt++) {
            int n = warp_n * 32 + nt * 8 + lq;
            bh[nt][0] = Bs[0][lr * BSTR32 + n];
            bh[nt][1] = Bs[0][(lr + 4) * BSTR32 + n];
            bl[nt][0] = Bs[1][lr * BSTR32 + n];
            bl[nt][1] = Bs[1][(lr + 4) * BSTR32 + n];
        }
        #pragma unroll
        for (int mt = 0; mt < 2; mt++)
            #pragma unroll
            for (int nt = 0; nt < 4; nt++) {
                MMA_BF16(c[mt][nt], ah[mt], bh[nt]);
                MMA_BF16(c[mt][nt], al[mt], bh[nt]);
                MMA_BF16(c[mt][nt], ah[mt], bl[nt]);
            }
        __syncthreads();
    }

    // --- epilogue: whole 64-col block lives in exactly one segment ---
    int y = blockIdx.y;
    float* dstbuf; int segoff; int rowstride;
    if      (y < 4)  { dstbuf = g_q;    segoff = col0;       rowstride = 256; }
    else if (y < 8)  { dstbuf = g_k;    segoff = col0 - 256; rowstride = 256; }
    else if (y < 12) { dstbuf = g_v;    segoff = col0 - 512; rowstride = 256; }
    else             { dstbuf = g_skip; segoff = 0;          rowstride = 64;  }

    #pragma unroll
    for (int mt = 0; mt < 2; mt++) {
        int r = row0 + warp_m * 32 + mt * 16 + lq;
        #pragma unroll
        for (int nt = 0; nt < 4; nt++) {
            int jc_in = warp_n * 32 + nt * 8 + lr * 2;   // in-block col
            float b0 = g_bc[col0 + jc_in];
            float b1 = g_bc[col0 + jc_in + 1];
            if (r < N) {
                float2 o = make_float2(c[mt][nt][0] + b0, c[mt][nt][1] + b1);
                *(float2*)&dstbuf[(size_t)r * rowstride + segoff + jc_in] = o;
            }
            if (r + 8 < N) {
                float2 o = make_float2(c[mt][nt][2] + b0, c[mt][nt][3] + b1);
                *(float2*)&dstbuf[(size_t)(r + 8) * rowstride + segoff + jc_in] = o;
            }
        }
    }
}

// ---------------- fused pass1: logits + exp + segment-sum z (warp per edge) ----------
__global__ void edge_logits_exp(const int* __restrict__ ei, int E) {
    int w    = (blockIdx.x * blockDim.x + threadIdx.x) >> 5;
    int lane = threadIdx.x & 31;
    if (w >= E) return;
    int src = ei[w], dst = ei[E + w];
    const float4* qd = (const float4*)&g_q[(size_t)dst * QK];
    const float4* ks = (const float4*)&g_k[(size_t)src * QK];
    float ev[2];
    #pragma unroll
    for (int it = 0; it < 2; it++) {
        int idx = it * 32 + lane;
        float4 a = qd[idx], b = ks[idx];
        float p = a.x * b.x + a.y * b.y + a.z * b.z + a.w * b.w;
        p += __shfl_xor_sync(0xffffffffu, p, 1);
        p += __shfl_xor_sync(0xffffffffu, p, 2);
        p += __shfl_xor_sync(0xffffffffu, p, 4);
        p += __shfl_xor_sync(0xffffffffu, p, 8);
        ev[it] = __expf(p * 0.125f);     // 1/sqrt(64)
    }
    float y0 = __shfl_sync(0xffffffffu, ev[0], 16);
    float y1 = __shfl_sync(0xffffffffu, ev[1], 16);
    if (lane == 0) {
        float4 e4 = make_float4(ev[0], y0, ev[1], y1);
        *(float4*)&g_sew[(size_t)w * 4] = e4;
        red_add_v4(&g_z[(size_t)dst * 4], e4.x, e4.y, e4.z, e4.w);
    }
}

// ---------------- pass3 (head-mean folded): agg64[dst] += sum_h (alpha_h/4)*v[src][h] ----
__global__ void edge_agg(const int* __restrict__ ei, int E) {
    int gid  = blockIdx.x * blockDim.x + threadIdx.x;
    int e    = gid >> 4;
    int l    = gid & 15;
    if (e >= E) return;
    int src = ei[e], dst = ei[E + e];
    float4 ev = *(const float4*)&g_sew[(size_t)e * 4];
    float4 zz = *(const float4*)&g_z[(size_t)dst * 4];
    float w0 = 0.25f * ev.x / zz.x;
    float w1 = 0.25f * ev.y / zz.y;
    float w2 = 0.25f * ev.z / zz.z;
    float w3 = 0.25f * ev.w / zz.w;
    const float* vb = &g_v[(size_t)src * QK + l * 4];
    float4 a = *(const float4*)(vb);
    float4 b = *(const float4*)(vb + 64);
    float4 c = *(const float4*)(vb + 128);
    float4 d = *(const float4*)(vb + 192);
    float o0 = w0 * a.x + w1 * b.x + w2 * c.x + w3 * d.x;
    float o1 = w0 * a.y + w1 * b.y + w2 * c.y + w3 * d.y;
    float o2 = w0 * a.z + w1 * b.z + w2 * c.z + w3 * d.z;
    float o3 = w0 * a.w + w1 * b.w + w2 * c.w + w3 * d.w;
    red_add_v4(&g_agg[(size_t)dst * HID + l * 4], o0, o1, o2, o3);
}

// ---------------- finalize: relu(agg + skip) ----------------
__global__ void finalize_conv(float* __restrict__ out, int N) {
    int idx = blockIdx.x * blockDim.x + threadIdx.x;   // over N*16 float4s
    if (idx >= N * (HID / 4)) return;
    float4 ag = *(const float4*)&g_agg[(size_t)idx * 4];
    float4 sk = *(const float4*)&g_skip[(size_t)idx * 4];
    float4 o;
    o.x = fmaxf(ag.x + sk.x, 0.f);
    o.y = fmaxf(ag.y + sk.y, 0.f);
    o.z = fmaxf(ag.z + sk.z, 0.f);
    o.w = fmaxf(ag.w + sk.w, 0.f);
    *(float4*)&out[(size_t)idx * 4] = o;
}

// ---------------- pool: per-graph mean of g_h2 (batch is sorted) ----------------
__global__ void pool_kernel(const int* __restrict__ batch, int N) {
    const int NPB = 256;
    int d = threadIdx.x;           // 0..63
    int n0 = blockIdx.x * NPB;
    int n1 = min(n0 + NPB, N);
    float acc = 0.f, cnt = 0.f;
    int cur = -1;
    for (int n = n0; n < n1; n++) {
        int g = batch[n];
        if (g != cur) {
            if (cur >= 0) {
                atomicAdd(&g_gsum[cur * HID + d], acc);
                if (d == 0) atomicAdd(&g_gcnt[cur], cnt);
            }
            cur = g; acc = 0.f; cnt = 0.f;
        }
        acc += g_h2[(size_t)n * HID + d];
        cnt += 1.f;
    }
    if (cur >= 0) {
        atomicAdd(&g_gsum[cur * HID + d], acc);
        if (d == 0) atomicAdd(&g_gcnt[cur], cnt);
    }
}

// ---------------- head: global MLP + concat + classifier (single block) ----------------
__global__ void head_kernel(const float* __restrict__ gf,
                            const float* __restrict__ gW1, const float* __restrict__ gb1,
                            const float* __restrict__ gW2, const float* __restrict__ gb2,
                            const float* __restrict__ hW1, const float* __restrict__ hb1,
                            const float* __restrict__ hW2, const float* __restrict__ hb2,
                            float* __restrict__ out) {
    __shared__ float sm_patch[NGRAPH * HID];
    __shared__ float sm_A[NGRAPH * HID];
    __shared__ float sm_B[NGRAPH * HID];
    int tid = threadIdx.x;

    for (int idx = tid; idx < NGRAPH * HID; idx += blockDim.x) {
        int g = idx >> 6;
        sm_patch[idx] = g_gsum[idx] / fmaxf(g_gcnt[g], 1.f);
    }
    __syncthreads();
    for (int idx = tid; idx < NGRAPH * HID; idx += blockDim.x) {
        int g = idx >> 6, j = idx & 63;
        float s = gb1[j];
        for (int k = 0; k < GDIM; k++) s += gf[g * GDIM + k] * gW1[k * HID + j];
        sm_A[idx] = fmaxf(s, 0.f);
    }
    __syncthreads();
    for (int idx = tid; idx < NGRAPH * HID; idx += blockDim.x) {
        int g = idx >> 6, j = idx & 63;
        float s = gb2[j];
        for (int k = 0; k < HID; k++) s += sm_A[g * HID + k] * gW2[k * HID + j];
        sm_B[idx] = fmaxf(s, 0.f);
    }
    __syncthreads();
    for (int idx = tid; idx < NGRAPH * HID; idx += blockDim.x) {
        int g = idx >> 6, j = idx & 63;
        float s = hb1[j];
        for (int k = 0; k < HID; k++) s += sm_patch[g * HID + k] * hW1[k * HID + j];
        for (int k = 0; k < HID; k++) s += sm_B[g * HID + k] * hW1[(HID + k) * HID + j];
        sm_A[idx] = fmaxf(s, 0.f);
    }
    __syncthreads();
    for (int idx = tid; idx < NGRAPH * NCLS; idx += blockDim.x) {
        int g = idx / NCLS, j = idx - g * NCLS;
        float s = hb2[j];
        for (int k = 0; k < HID; k++) s += sm_A[g * HID + k] * hW2[k * NCLS + j];
        out[idx] = s;
    }
}

// ---------------- host orchestration ----------------
static void run_conv(const float* xin, int K, int N, int E, const int* ei,
                     const float* Wq, const float* bq, const float* Wk, const float* bk,
                     const float* Wv, const float* bv, const float* Ws, const float* bs,
                     float* hout, void* z_p, void* agg_p) {
    pack_w<<<(K * OCT + 255) / 256, 256>>>(Wq, bq, Wk, bk, Wv, bv, Ws, bs, K);
    cudaMemsetAsync(z_p,   0, (size_t)N * HEADS * sizeof(float), 0);
    cudaMemsetAsync(agg_p, 0, (size_t)N * HID * sizeof(float), 0);
    dim3 gg((N + 127) / 128, OCT / 64);
    gemm_qkvs<<<gg, 256>>>(xin, N, K);
    int lthreads = E * 32;
    edge_logits_exp<<<(lthreads + 255) / 256, 256>>>(ei, E);
    int athreads = E * 16;
    edge_agg<<<(athreads + 255) / 256, 256>>>(ei, E);
    finalize_conv<<<(N * (HID / 4) + 255) / 256, 256>>>(hout, N);
}

extern "C" void kernel_launch(void* const* d_in, const int* in_sizes, int n_in,
                              void* d_out, int out_size) {
    const float* x     = (const float*)d_in[0];
    const int*   ei    = (const int*)  d_in[1];
    const int*   batch = (const int*)  d_in[2];
    const float* gf    = (const float*)d_in[3];
    const float* c1[8]; for (int i = 0; i < 8; i++) c1[i] = (const float*)d_in[4 + i];
    const float* c2[8]; for (int i = 0; i < 8; i++) c2[i] = (const float*)d_in[12 + i];
    const float* gW1 = (const float*)d_in[20]; const float* gb1 = (const float*)d_in[21];
    const float* gW2 = (const float*)d_in[22]; const float* gb2 = (const float*)d_in[23];
    const float* hW1 = (const float*)d_in[24]; const float* hb1 = (const float*)d_in[25];
    const float* hW2 = (const float*)d_in[26]; const float* hb2 = (const float*)d_in[27];

    int N = in_sizes[0] / 128;
    int E = in_sizes[1] / 2;

    void *p_h1, *p_h2, *p_z, *p_agg, *p_gsum, *p_gcnt;
    cudaGetSymbolAddress(&p_h1,   g_h1);
    cudaGetSymbolAddress(&p_h2,   g_h2);
    cudaGetSymbolAddress(&p_z,    g_z);
    cudaGetSymbolAddress(&p_agg,  g_agg);
    cudaGetSymbolAddress(&p_gsum, g_gsum);
    cudaGetSymbolAddress(&p_gcnt, g_gcnt);

    // conv1 (in=128)
    run_conv(x, 128, N, E, ei,
             c1[0], c1[1], c1[2], c1[3], c1[4], c1[5], c1[6], c1[7],
             (float*)p_h1, p_z, p_agg);
    // conv2 (in=64)
    run_conv((const float*)p_h1, 64, N, E, ei,
             c2[0], c2[1], c2[2], c2[3], c2[4], c2[5], c2[6], c2[7],
             (float*)p_h2, p_z, p_agg);

    // pooling
    cudaMemsetAsync(p_gsum, 0, NGRAPH * HID * sizeof(float), 0);
    cudaMemsetAsync(p_gcnt, 0, NGRAPH * sizeof(float), 0);
    pool_kernel<<<(N + 255) / 256, HID>>>(batch, N);

    // head
    head_kernel<<<1, 256>>>(gf, gW1, gb1, gW2, gb2, hW1, hb1, hW2, hb2, (float*)d_out);
}

// round 7
// speedup vs baseline: 1.3533x; 1.0550x over previous
#include <cuda_runtime.h>
#include <cuda_bf16.h>
#include <math.h>
#include <cstdint>

// Problem constants
#define NMAX   50000
#define EMAX   800000
#define HEADS  4
#define HID    64
#define QK     256        // HEADS*HID
#define OCT    832        // 3*QK + HID
#define NGRAPH 64
#define GDIM   256
#define NCLS   10

// ---------------- scratch (device globals; no runtime allocation) ----------------
__device__ __align__(16) __nv_bfloat16 g_qb[NMAX * QK];   // bf16 q (logits only)
__device__ __align__(16) __nv_bfloat16 g_kb[NMAX * QK];   // bf16 k (logits only)
__device__ __align__(16) float    g_v   [NMAX * QK];
__device__ __align__(16) float    g_skip[NMAX * HID];
__device__ __align__(16) float    g_agg [NMAX * HID];   // head-mean folded
__device__ __align__(16) float    g_h1  [NMAX * HID];
__device__ __align__(16) float    g_h2  [NMAX * HID];
__device__ __align__(16) float    g_sew [EMAX * HEADS];
__device__ __align__(16) float    g_z   [NMAX * HEADS];
__device__ __align__(16) float    g_Wc  [128 * OCT];
__device__ __align__(16) float    g_bc  [OCT];
__device__ __align__(16) float    g_gsum[NGRAPH * HID];
__device__ __align__(16) float    g_gcnt[NGRAPH];

// ---------------- helpers ----------------
__device__ __forceinline__ void red_add_v4(float* p, float a, float b, float c, float d) {
    asm volatile("red.global.add.v4.f32 [%0], {%1,%2,%3,%4};"
                 :: "l"(p), "f"(a), "f"(b), "f"(c), "f"(d) : "memory");
}
// pack two fp32 into one uint32 of two bf16 (lo half = first)
__device__ __forceinline__ uint32_t pack_bf16(float a, float b) {
    __nv_bfloat16 ha = __float2bfloat16_rn(a);
    __nv_bfloat16 hb = __float2bfloat16_rn(b);
    return (uint32_t)__bfloat16_as_ushort(ha) | ((uint32_t)__bfloat16_as_ushort(hb) << 16);
}
__device__ __forceinline__ float bf_hi_res(float v) {   // v - bf16(v)
    return v - __bfloat162float(__float2bfloat16_rn(v));
}
// dot of 2 bf16 pairs packed as uint32 (bf16->fp32 = shift<<16)
__device__ __forceinline__ float dot2bf(uint32_t ua, uint32_t ub) {
    float a0 = __uint_as_float(ua << 16);
    float a1 = __uint_as_float(ua & 0xffff0000u);
    float b0 = __uint_as_float(ub << 16);
    float b1 = __uint_as_float(ub & 0xffff0000u);
    return a0 * b0 + a1 * b1;
}

#define MMA_BF16(c, a, b)                                                     \
    asm volatile("mma.sync.aligned.m16n8k16.row.col.f32.bf16.bf16.f32 "       \
                 "{%0,%1,%2,%3}, {%4,%5,%6,%7}, {%8,%9}, {%0,%1,%2,%3};"      \
                 : "+f"((c)[0]), "+f"((c)[1]), "+f"((c)[2]), "+f"((c)[3])     \
                 : "r"((a)[0]), "r"((a)[1]), "r"((a)[2]), "r"((a)[3]),        \
                   "r"((b)[0]), "r"((b)[1]))

// ---------------- weight pack: Wc[K][832] = [Wq|Wk|Wv|Ws], bc[832] ----------------
__global__ void pack_w(const float* __restrict__ Wq, const float* __restrict__ bq,
                       const float* __restrict__ Wk, const float* __restrict__ bk,
                       const float* __restrict__ Wv, const float* __restrict__ bv,
                       const float* __restrict__ Ws, const float* __restrict__ bs, int K) {
    int idx = blockIdx.x * blockDim.x + threadIdx.x;
    int tot = K * OCT;
    if (idx < tot) {
        int k = idx / OCT, j = idx - k * OCT;
        float v;
        if      (j < 256) v = Wq[k * 256 + j];
        else if (j < 512) v = Wk[k * 256 + (j - 256)];
        else if (j < 768) v = Wv[k * 256 + (j - 512)];
        else              v = Ws[k * 64  + (j - 768)];
        g_Wc[idx] = v;
    }
    if (idx < OCT) {
        float b;
        if      (idx < 256) b = bq[idx];
        else if (idx < 512) b = bk[idx - 256];
        else if (idx < 768) b = bv[idx - 512];
        else                b = bs[idx - 768];
        g_bc[idx] = b;
    }
}

// ---------------- GEMM: C[N,832] = A[N,K] @ Wc[K,832] + bc ; routed to q/k/v/skip ----
// 3xBF16-split tensor-core GEMM via mma.sync.m16n8k16. q,k stored as bf16.
#define ASTR32 136
#define BSTR32 72
__global__ void __launch_bounds__(256, 2) gemm_qkvs(const float* __restrict__ A, int N, int K) {
    __shared__ uint32_t As[2][8 * ASTR32];   // [hi/lo][kpair][m]
    __shared__ uint32_t Bs[2][8 * BSTR32];   // [hi/lo][kpair][n]
    const int t    = threadIdx.x;
    const int lane = t & 31, wid = t >> 5;
    const int warp_m = wid & 3;          // 0..3 -> 32-row slab
    const int warp_n = wid >> 2;         // 0..1 -> 32-col slab
    const int row0 = blockIdx.x * 128, col0 = blockIdx.y * 64;
    const int lq = lane >> 2;            // 0..7
    const int lr = lane & 3;             // 0..3

    float c[2][4][4];
    #pragma unroll
    for (int mt = 0; mt < 2; mt++)
        #pragma unroll
        for (int nt = 0; nt < 4; nt++)
            #pragma unroll
            for (int i = 0; i < 4; i++) c[mt][nt][i] = 0.f;

    for (int k0 = 0; k0 < K; k0 += 16) {
        // --- stage A 128x16 -> As[hi/lo][kp][m] packed k-pairs ---
        #pragma unroll
        for (int ii = 0; ii < 2; ii++) {
            int idx = t + ii * 256;
            int r = idx >> 2, cg = (idx & 3) << 2;   // cg in {0,4,8,12}
            int gr = row0 + r;
            float4 a = (gr < N) ? *(const float4*)&A[(size_t)gr * K + k0 + cg]
                                : make_float4(0.f, 0.f, 0.f, 0.f);
            int kp = cg >> 1;
            As[0][kp * ASTR32 + r]       = pack_bf16(a.x, a.y);
            As[0][(kp + 1) * ASTR32 + r] = pack_bf16(a.z, a.w);
            As[1][kp * ASTR32 + r]       = pack_bf16(bf_hi_res(a.x), bf_hi_res(a.y));
            As[1][(kp + 1) * ASTR32 + r] = pack_bf16(bf_hi_res(a.z), bf_hi_res(a.w));
        }
        // --- stage B 16x64 -> Bs[hi/lo][kp][n] packed over k ---
        if (t < 128) {
            int kp = t >> 4, j4 = (t & 15) << 2;
            const float* r0p = &g_Wc[(size_t)(k0 + 2 * kp) * OCT + col0 + j4];
            const float* r1p = r0p + OCT;
            float4 b0 = *(const float4*)r0p;
            float4 b1 = *(const float4*)r1p;
            float v0[4] = {b0.x, b0.y, b0.z, b0.w};
            float v1[4] = {b1.x, b1.y, b1.z, b1.w};
            #pragma unroll
            for (int i = 0; i < 4; i++) {
                Bs[0][kp * BSTR32 + j4 + i] = pack_bf16(v0[i], v1[i]);
                Bs[1][kp * BSTR32 + j4 + i] = pack_bf16(bf_hi_res(v0[i]), bf_hi_res(v1[i]));
            }
        }
        __syncthreads();

        // --- fragments + MMAs (one k16 step per tile) ---
        uint32_t ah[2][4], al[2][4];
        #pragma unroll
        for (int mt = 0; mt < 2; mt++) {
            int r0 = warp_m * 32 + mt * 16 + lq;
            ah[mt][0] = As[0][lr * ASTR32 + r0];
            ah[mt][1] = As[0][lr * ASTR32 + r0 + 8];
            ah[mt][2] = As[0][(lr + 4) * ASTR32 + r0];
            ah[mt][3] = As[0][(lr + 4) * ASTR32 + r0 + 8];
            al[mt][0] = As[1][lr * ASTR32 + r0];
            al[mt][1] = As[1][lr * ASTR32 + r0 + 8];
            al[mt][2] = As[1][(lr + 4) * ASTR32 + r0];
            al[mt][3] = As[1][(lr + 4) * ASTR32 + r0 + 8];
        }
        uint32_t bh[4][2], bl[4][2];
        #pragma unroll
        for (int nt = 0; nt < 4; nt++) {
            int n = warp_n * 32 + nt * 8 + lq;
            bh[nt][0] = Bs[0][lr * BSTR32 + n];
            bh[nt][1] = Bs[0][(lr + 4) * BSTR32 + n];
            bl[nt][0] = Bs[1][lr * BSTR32 + n];
            bl[nt][1] = Bs[1][(lr + 4) * BSTR32 + n];
        }
        #pragma unroll
        for (int mt = 0; mt < 2; mt++)
            #pragma unroll
            for (int nt = 0; nt < 4; nt++) {
                MMA_BF16(c[mt][nt], ah[mt], bh[nt]);
                MMA_BF16(c[mt][nt], al[mt], bh[nt]);
                MMA_BF16(c[mt][nt], ah[mt], bl[nt]);
            }
        __syncthreads();
    }

    // --- epilogue: route. q/k -> bf16 packed; v/skip -> fp32 ---
    int y = blockIdx.y;
    bool is_bf  = (y < 8);
    __nv_bfloat16* bfdst = (y < 4) ? g_qb : g_kb;
    int bfoff = (y < 4) ? col0 : col0 - 256;
    float* fdst; int segoff; int rowstride;
    if (y < 12) { fdst = g_v;    segoff = col0 - 512; rowstride = 256; }
    else        { fdst = g_skip; segoff = 0;          rowstride = 64;  }

    #pragma unroll
    for (int mt = 0; mt < 2; mt++) {
        int r = row0 + warp_m * 32 + mt * 16 + lq;
        #pragma unroll
        for (int nt = 0; nt < 4; nt++) {
            int jc_in = warp_n * 32 + nt * 8 + lr * 2;   // in-block col (even)
            float b0 = g_bc[col0 + jc_in];
            float b1 = g_bc[col0 + jc_in + 1];
            if (is_bf) {
                if (r < N) {
                    *(uint32_t*)&bfdst[(size_t)r * 256 + bfoff + jc_in] =
                        pack_bf16(c[mt][nt][0] + b0, c[mt][nt][1] + b1);
                }
                if (r + 8 < N) {
                    *(uint32_t*)&bfdst[(size_t)(r + 8) * 256 + bfoff + jc_in] =
                        pack_bf16(c[mt][nt][2] + b0, c[mt][nt][3] + b1);
                }
            } else {
                if (r < N) {
                    float2 o = make_float2(c[mt][nt][0] + b0, c[mt][nt][1] + b1);
                    *(float2*)&fdst[(size_t)r * rowstride + segoff + jc_in] = o;
                }
                if (r + 8 < N) {
                    float2 o = make_float2(c[mt][nt][2] + b0, c[mt][nt][3] + b1);
                    *(float2*)&fdst[(size_t)(r + 8) * rowstride + segoff + jc_in] = o;
                }
            }
        }
    }
}

// ---------------- fused pass1: logits + exp + segment-sum z (warp per edge, bf16) ----
// lane loads 8 bf16 of q[dst] and k[src]; 8-lane groups = one head each.
__global__ void edge_logits_exp(const int* __restrict__ ei, int E) {
    int w    = (blockIdx.x * blockDim.x + threadIdx.x) >> 5;
    int lane = threadIdx.x & 31;
    if (w >= E) return;
    int src = ei[w], dst = ei[E + w];
    const uint4* qd = (const uint4*)&g_qb[(size_t)dst * QK];
    const uint4* ks = (const uint4*)&g_kb[(size_t)src * QK];
    uint4 a = qd[lane];
    uint4 b = ks[lane];
    float p = dot2bf(a.x, b.x) + dot2bf(a.y, b.y) + dot2bf(a.z, b.z) + dot2bf(a.w, b.w);
    p += __shfl_xor_sync(0xffffffffu, p, 1);
    p += __shfl_xor_sync(0xffffffffu, p, 2);
    p += __shfl_xor_sync(0xffffffffu, p, 4);
    // heads at lanes 0, 8, 16, 24
    float p1 = __shfl_sync(0xffffffffu, p, 8);
    float p2 = __shfl_sync(0xffffffffu, p, 16);
    float p3 = __shfl_sync(0xffffffffu, p, 24);
    if (lane == 0) {
        float4 e4;
        e4.x = __expf(p  * 0.125f);
        e4.y = __expf(p1 * 0.125f);
        e4.z = __expf(p2 * 0.125f);
        e4.w = __expf(p3 * 0.125f);
        *(float4*)&g_sew[(size_t)w * 4] = e4;
        red_add_v4(&g_z[(size_t)dst * 4], e4.x, e4.y, e4.z, e4.w);
    }
}

// ---------------- pass3 (head-mean folded): agg64[dst] += sum_h (alpha_h/4)*v[src][h] ----
__global__ void edge_agg(const int* __restrict__ ei, int E) {
    int gid  = blockIdx.x * blockDim.x + threadIdx.x;
    int e    = gid >> 4;
    int l    = gid & 15;
    if (e >= E) return;
    int src = ei[e], dst = ei[E + e];
    float4 ev = *(const float4*)&g_sew[(size_t)e * 4];
    float4 zz = *(const float4*)&g_z[(size_t)dst * 4];
    float w0 = 0.25f * ev.x / zz.x;
    float w1 = 0.25f * ev.y / zz.y;
    float w2 = 0.25f * ev.z / zz.z;
    float w3 = 0.25f * ev.w / zz.w;
    const float* vb = &g_v[(size_t)src * QK + l * 4];
    float4 a = *(const float4*)(vb);
    float4 b = *(const float4*)(vb + 64);
    float4 c = *(const float4*)(vb + 128);
    float4 d = *(const float4*)(vb + 192);
    float o0 = w0 * a.x + w1 * b.x + w2 * c.x + w3 * d.x;
    float o1 = w0 * a.y + w1 * b.y + w2 * c.y + w3 * d.y;
    float o2 = w0 * a.z + w1 * b.z + w2 * c.z + w3 * d.z;
    float o3 = w0 * a.w + w1 * b.w + w2 * c.w + w3 * d.w;
    red_add_v4(&g_agg[(size_t)dst * HID + l * 4], o0, o1, o2, o3);
}

// ---------------- finalize: relu(agg + skip) ----------------
__global__ void finalize_conv(float* __restrict__ out, int N) {
    int idx = blockIdx.x * blockDim.x + threadIdx.x;   // over N*16 float4s
    if (idx >= N * (HID / 4)) return;
    float4 ag = *(const float4*)&g_agg[(size_t)idx * 4];
    float4 sk = *(const float4*)&g_skip[(size_t)idx * 4];
    float4 o;
    o.x = fmaxf(ag.x + sk.x, 0.f);
    o.y = fmaxf(ag.y + sk.y, 0.f);
    o.z = fmaxf(ag.z + sk.z, 0.f);
    o.w = fmaxf(ag.w + sk.w, 0.f);
    *(float4*)&out[(size_t)idx * 4] = o;
}

// ---------------- pool: per-graph mean of g_h2 (batch is sorted) ----------------
__global__ void pool_kernel(const int* __restrict__ batch, int N) {
    const int NPB = 256;
    int d = threadIdx.x;           // 0..63
    int n0 = blockIdx.x * NPB;
    int n1 = min(n0 + NPB, N);
    float acc = 0.f, cnt = 0.f;
    int cur = -1;
    for (int n = n0; n < n1; n++) {
        int g = batch[n];
        if (g != cur) {
            if (cur >= 0) {
                atomicAdd(&g_gsum[cur * HID + d], acc);
                if (d == 0) atomicAdd(&g_gcnt[cur], cnt);
            }
            cur = g; acc = 0.f; cnt = 0.f;
        }
        acc += g_h2[(size_t)n * HID + d];
        cnt += 1.f;
    }
    if (cur >= 0) {
        atomicAdd(&g_gsum[cur * HID + d], acc);
        if (d == 0) atomicAdd(&g_gcnt[cur], cnt);
    }
}

// ---------------- head: global MLP + concat + classifier (single block) ----------------
__global__ void head_kernel(const float* __restrict__ gf,
                            const float* __restrict__ gW1, const float* __restrict__ gb1,
                            const float* __restrict__ gW2, const float* __restrict__ gb2,
                            const float* __restrict__ hW1, const float* __restrict__ hb1,
                            const float* __restrict__ hW2, const float* __restrict__ hb2,
                            float* __restrict__ out) {
    __shared__ float sm_patch[NGRAPH * HID];
    __shared__ float sm_A[NGRAPH * HID];
    __shared__ float sm_B[NGRAPH * HID];
    int tid = threadIdx.x;

    for (int idx = tid; idx < NGRAPH * HID; idx += blockDim.x) {
        int g = idx >> 6;
        sm_patch[idx] = g_gsum[idx] / fmaxf(g_gcnt[g], 1.f);
    }
    __syncthreads();
    for (int idx = tid; idx < NGRAPH * HID; idx += blockDim.x) {
        int g = idx >> 6, j = idx & 63;
        float s = gb1[j];
        for (int k = 0; k < GDIM; k++) s += gf[g * GDIM + k] * gW1[k * HID + j];
        sm_A[idx] = fmaxf(s, 0.f);
    }
    __syncthreads();
    for (int idx = tid; idx < NGRAPH * HID; idx += blockDim.x) {
        int g = idx >> 6, j = idx & 63;
        float s = gb2[j];
        for (int k = 0; k < HID; k++) s += sm_A[g * HID + k] * gW2[k * HID + j];
        sm_B[idx] = fmaxf(s, 0.f);
    }
    __syncthreads();
    for (int idx = tid; idx < NGRAPH * HID; idx += blockDim.x) {
        int g = idx >> 6, j = idx & 63;
        float s = hb1[j];
        for (int k = 0; k < HID; k++) s += sm_patch[g * HID + k] * hW1[k * HID + j];
        for (int k = 0; k < HID; k++) s += sm_B[g * HID + k] * hW1[(HID + k) * HID + j];
        sm_A[idx] = fmaxf(s, 0.f);
    }
    __syncthreads();
    for (int idx = tid; idx < NGRAPH * NCLS; idx += blockDim.x) {
        int g = idx / NCLS, j = idx - g * NCLS;
        float s = hb2[j];
        for (int k = 0; k < HID; k++) s += sm_A[g * HID + k] * hW2[k * NCLS + j];
        out[idx] = s;
    }
}

// ---------------- host orchestration ----------------
static void run_conv(const float* xin, int K, int N, int E, const int* ei,
                     const float* Wq, const float* bq, const float* Wk, const float* bk,
                     const float* Wv, const float* bv, const float* Ws, const float* bs,
                     float* hout, void* z_p, void* agg_p) {
    pack_w<<<(K * OCT + 255) / 256, 256>>>(Wq, bq, Wk, bk, Wv, bv, Ws, bs, K);
    cudaMemsetAsync(z_p,   0, (size_t)N * HEADS * sizeof(float), 0);
    cudaMemsetAsync(agg_p, 0, (size_t)N * HID * sizeof(float), 0);
    dim3 gg((N + 127) / 128, OCT / 64);
    gemm_qkvs<<<gg, 256>>>(xin, N, K);
    int lthreads = E * 32;
    edge_logits_exp<<<(lthreads + 255) / 256, 256>>>(ei, E);
    int athreads = E * 16;
    edge_agg<<<(athreads + 255) / 256, 256>>>(ei, E);
    finalize_conv<<<(N * (HID / 4) + 255) / 256, 256>>>(hout, N);
}

extern "C" void kernel_launch(void* const* d_in, const int* in_sizes, int n_in,
                              void* d_out, int out_size) {
    const float* x     = (const float*)d_in[0];
    const int*   ei    = (const int*)  d_in[1];
    const int*   batch = (const int*)  d_in[2];
    const float* gf    = (const float*)d_in[3];
    const float* c1[8]; for (int i = 0; i < 8; i++) c1[i] = (const float*)d_in[4 + i];
    const float* c2[8]; for (int i = 0; i < 8; i++) c2[i] = (const float*)d_in[12 + i];
    const float* gW1 = (const float*)d_in[20]; const float* gb1 = (const float*)d_in[21];
    const float* gW2 = (const float*)d_in[22]; const float* gb2 = (const float*)d_in[23];
    const float* hW1 = (const float*)d_in[24]; const float* hb1 = (const float*)d_in[25];
    const float* hW2 = (const float*)d_in[26]; const float* hb2 = (const float*)d_in[27];

    int N = in_sizes[0] / 128;
    int E = in_sizes[1] / 2;

    void *p_h1, *p_h2, *p_z, *p_agg, *p_gsum, *p_gcnt;
    cudaGetSymbolAddress(&p_h1,   g_h1);
    cudaGetSymbolAddress(&p_h2,   g_h2);
    cudaGetSymbolAddress(&p_z,    g_z);
    cudaGetSymbolAddress(&p_agg,  g_agg);
    cudaGetSymbolAddress(&p_gsum, g_gsum);
    cudaGetSymbolAddress(&p_gcnt, g_gcnt);

    // conv1 (in=128)
    run_conv(x, 128, N, E, ei,
             c1[0], c1[1], c1[2], c1[3], c1[4], c1[5], c1[6], c1[7],
             (float*)p_h1, p_z, p_agg);
    // conv2 (in=64)
    run_conv((const float*)p_h1, 64, N, E, ei,
             c2[0], c2[1], c2[2], c2[3], c2[4], c2[5], c2[6], c2[7],
             (float*)p_h2, p_z, p_agg);

    // pooling
    cudaMemsetAsync(p_gsum, 0, NGRAPH * HID * sizeof(float), 0);
    cudaMemsetAsync(p_gcnt, 0, NGRAPH * sizeof(float), 0);
    pool_kernel<<<(N + 255) / 256, HID>>>(batch, N);

    // head
    head_kernel<<<1, 256>>>(gf, gW1, gb1, gW2, gb2, hW1, hb1, hW2, hb2, (float*)d_out);
}

// round 8
// speedup vs baseline: 1.8106x; 1.3379x over previous
#include <cuda_runtime.h>
#include <cuda_bf16.h>
#include <math.h>
#include <cstdint>

// Problem constants
#define NMAX   50000
#define EMAX   800000
#define HEADS  4
#define HID    64
#define QK     256        // HEADS*HID
#define OCT    832        // 3*QK + HID
#define NGRAPH 64
#define GDIM   256
#define NCLS   10

// ---------------- scratch (device globals; no runtime allocation) ----------------
__device__ __align__(16) __nv_bfloat16 g_qb[NMAX * QK];   // bf16 q (logits only)
__device__ __align__(16) __nv_bfloat16 g_kb[NMAX * QK];   // bf16 k (logits only)
__device__ __align__(16) float    g_v   [NMAX * QK];
__device__ __align__(16) float    g_skip[NMAX * HID];
__device__ __align__(16) float    g_agg [NMAX * HID];   // head-mean folded
__device__ __align__(16) float    g_h1  [NMAX * HID];
__device__ __align__(16) float    g_h2  [NMAX * HID];
__device__ __align__(16) float    g_sew [EMAX * HEADS];
__device__ __align__(16) float    g_z   [NMAX * HEADS];
__device__ __align__(16) float    g_Wc  [128 * OCT];
__device__ __align__(16) float    g_bc  [OCT];
__device__ __align__(16) float    g_gsum[NGRAPH * HID];
__device__ __align__(16) float    g_gcnt[NGRAPH];

// ---------------- helpers ----------------
__device__ __forceinline__ void red_add_v4(float* p, float a, float b, float c, float d) {
    asm volatile("red.global.add.v4.f32 [%0], {%1,%2,%3,%4};"
                 :: "l"(p), "f"(a), "f"(b), "f"(c), "f"(d) : "memory");
}
// pack two fp32 into one uint32 of two bf16 (lo half = first)
__device__ __forceinline__ uint32_t pack_bf16(float a, float b) {
    __nv_bfloat16 ha = __float2bfloat16_rn(a);
    __nv_bfloat16 hb = __float2bfloat16_rn(b);
    return (uint32_t)__bfloat16_as_ushort(ha) | ((uint32_t)__bfloat16_as_ushort(hb) << 16);
}
__device__ __forceinline__ float bf_hi_res(float v) {   // v - bf16(v)
    return v - __bfloat162float(__float2bfloat16_rn(v));
}
// dot of 2 bf16 pairs packed as uint32 (bf16->fp32 = shift<<16)
__device__ __forceinline__ float dot2bf(uint32_t ua, uint32_t ub) {
    float a0 = __uint_as_float(ua << 16);
    float a1 = __uint_as_float(ua & 0xffff0000u);
    float b0 = __uint_as_float(ub << 16);
    float b1 = __uint_as_float(ub & 0xffff0000u);
    return a0 * b0 + a1 * b1;
}

#define MMA_BF16(c, a, b)                                                     \
    asm volatile("mma.sync.aligned.m16n8k16.row.col.f32.bf16.bf16.f32 "       \
                 "{%0,%1,%2,%3}, {%4,%5,%6,%7}, {%8,%9}, {%0,%1,%2,%3};"      \
                 : "+f"((c)[0]), "+f"((c)[1]), "+f"((c)[2]), "+f"((c)[3])     \
                 : "r"((a)[0]), "r"((a)[1]), "r"((a)[2]), "r"((a)[3]),        \
                   "r"((b)[0]), "r"((b)[1]))

// ---------------- weight pack: Wc[K][832] = [Wq|Wk|Wv|Ws], bc[832] ----------------
__global__ void pack_w(const float* __restrict__ Wq, const float* __restrict__ bq,
                       const float* __restrict__ Wk, const float* __restrict__ bk,
                       const float* __restrict__ Wv, const float* __restrict__ bv,
                       const float* __restrict__ Ws, const float* __restrict__ bs, int K) {
    int idx = blockIdx.x * blockDim.x + threadIdx.x;
    int tot = K * OCT;
    if (idx < tot) {
        int k = idx / OCT, j = idx - k * OCT;
        float v;
        if      (j < 256) v = Wq[k * 256 + j];
        else if (j < 512) v = Wk[k * 256 + (j - 256)];
        else if (j < 768) v = Wv[k * 256 + (j - 512)];
        else              v = Ws[k * 64  + (j - 768)];
        g_Wc[idx] = v;
    }
    if (idx < OCT) {
        float b;
        if      (idx < 256) b = bq[idx];
        else if (idx < 512) b = bk[idx - 256];
        else if (idx < 768) b = bv[idx - 512];
        else                b = bs[idx - 768];
        g_bc[idx] = b;
    }
}

// ---------------- GEMM: C[N,832] = A[N,K] @ Wc[K,832] + bc ; routed to q/k/v/skip ----
// 3xBF16-split tensor-core GEMM via mma.sync.m16n8k16. q,k stored as bf16.
#define ASTR32 136
#define BSTR32 72
__global__ void __launch_bounds__(256, 2) gemm_qkvs(const float* __restrict__ A, int N, int K) {
    __shared__ uint32_t As[2][8 * ASTR32];   // [hi/lo][kpair][m]
    __shared__ uint32_t Bs[2][8 * BSTR32];   // [hi/lo][kpair][n]
    const int t    = threadIdx.x;
    const int lane = t & 31, wid = t >> 5;
    const int warp_m = wid & 3;          // 0..3 -> 32-row slab
    const int warp_n = wid >> 2;         // 0..1 -> 32-col slab
    const int row0 = blockIdx.x * 128, col0 = blockIdx.y * 64;
    const int lq = lane >> 2;            // 0..7
    const int lr = lane & 3;             // 0..3

    float c[2][4][4];
    #pragma unroll
    for (int mt = 0; mt < 2; mt++)
        #pragma unroll
        for (int nt = 0; nt < 4; nt++)
            #pragma unroll
            for (int i = 0; i < 4; i++) c[mt][nt][i] = 0.f;

    for (int k0 = 0; k0 < K; k0 += 16) {
        // --- stage A 128x16 -> As[hi/lo][kp][m] packed k-pairs ---
        #pragma unroll
        for (int ii = 0; ii < 2; ii++) {
            int idx = t + ii * 256;
            int r = idx >> 2, cg = (idx & 3) << 2;   // cg in {0,4,8,12}
            int gr = row0 + r;
            float4 a = (gr < N) ? *(const float4*)&A[(size_t)gr * K + k0 + cg]
                                : make_float4(0.f, 0.f, 0.f, 0.f);
            int kp = cg >> 1;
            As[0][kp * ASTR32 + r]       = pack_bf16(a.x, a.y);
            As[0][(kp + 1) * ASTR32 + r] = pack_bf16(a.z, a.w);
            As[1][kp * ASTR32 + r]       = pack_bf16(bf_hi_res(a.x), bf_hi_res(a.y));
            As[1][(kp + 1) * ASTR32 + r] = pack_bf16(bf_hi_res(a.z), bf_hi_res(a.w));
        }
        // --- stage B 16x64 -> Bs[hi/lo][kp][n] packed over k ---
        if (t < 128) {
            int kp = t >> 4, j4 = (t & 15) << 2;
            const float* r0p = &g_Wc[(size_t)(k0 + 2 * kp) * OCT + col0 + j4];
            const float* r1p = r0p + OCT;
            float4 b0 = *(const float4*)r0p;
            float4 b1 = *(const float4*)r1p;
            float v0[4] = {b0.x, b0.y, b0.z, b0.w};
            float v1[4] = {b1.x, b1.y, b1.z, b1.w};
            #pragma unroll
            for (int i = 0; i < 4; i++) {
                Bs[0][kp * BSTR32 + j4 + i] = pack_bf16(v0[i], v1[i]);
                Bs[1][kp * BSTR32 + j4 + i] = pack_bf16(bf_hi_res(v0[i]), bf_hi_res(v1[i]));
            }
        }
        __syncthreads();

        // --- fragments + MMAs (one k16 step per tile) ---
        uint32_t ah[2][4], al[2][4];
        #pragma unroll
        for (int mt = 0; mt < 2; mt++) {
            int r0 = warp_m * 32 + mt * 16 + lq;
            ah[mt][0] = As[0][lr * ASTR32 + r0];
            ah[mt][1] = As[0][lr * ASTR32 + r0 + 8];
            ah[mt][2] = As[0][(lr + 4) * ASTR32 + r0];
            ah[mt][3] = As[0][(lr + 4) * ASTR32 + r0 + 8];
            al[mt][0] = As[1][lr * ASTR32 + r0];
            al[mt][1] = As[1][lr * ASTR32 + r0 + 8];
            al[mt][2] = As[1][(lr + 4) * ASTR32 + r0];
            al[mt][3] = As[1][(lr + 4) * ASTR32 + r0 + 8];
        }
        uint32_t bh[4][2], bl[4][2];
        #pragma unroll
        for (int nt = 0; nt < 4; nt++) {
            int n = warp_n * 32 + nt * 8 + lq;
            bh[nt][0] = Bs[0][lr * BSTR32 + n];
            bh[nt][1] = Bs[0][(lr + 4) * BSTR32 + n];
            bl[nt][0] = Bs[1][lr * BSTR32 + n];
            bl[nt][1] = Bs[1][(lr + 4) * BSTR32 + n];
        }
        #pragma unroll
        for (int mt = 0; mt < 2; mt++)
            #pragma unroll
            for (int nt = 0; nt < 4; nt++) {
                MMA_BF16(c[mt][nt], ah[mt], bh[nt]);
                MMA_BF16(c[mt][nt], al[mt], bh[nt]);
                MMA_BF16(c[mt][nt], ah[mt], bl[nt]);
            }
        __syncthreads();
    }

    // --- epilogue: route. q/k -> bf16 packed; v/skip -> fp32 ---
    int y = blockIdx.y;
    bool is_bf  = (y < 8);
    __nv_bfloat16* bfdst = (y < 4) ? g_qb : g_kb;
    int bfoff = (y < 4) ? col0 : col0 - 256;
    float* fdst; int segoff; int rowstride;
    if (y < 12) { fdst = g_v;    segoff = col0 - 512; rowstride = 256; }
    else        { fdst = g_skip; segoff = 0;          rowstride = 64;  }

    #pragma unroll
    for (int mt = 0; mt < 2; mt++) {
        int r = row0 + warp_m * 32 + mt * 16 + lq;
        #pragma unroll
        for (int nt = 0; nt < 4; nt++) {
            int jc_in = warp_n * 32 + nt * 8 + lr * 2;   // in-block col (even)
            float b0 = g_bc[col0 + jc_in];
            float b1 = g_bc[col0 + jc_in + 1];
            if (is_bf) {
                if (r < N) {
                    *(uint32_t*)&bfdst[(size_t)r * 256 + bfoff + jc_in] =
                        pack_bf16(c[mt][nt][0] + b0, c[mt][nt][1] + b1);
                }
                if (r + 8 < N) {
                    *(uint32_t*)&bfdst[(size_t)(r + 8) * 256 + bfoff + jc_in] =
                        pack_bf16(c[mt][nt][2] + b0, c[mt][nt][3] + b1);
                }
            } else {
                if (r < N) {
                    float2 o = make_float2(c[mt][nt][0] + b0, c[mt][nt][1] + b1);
                    *(float2*)&fdst[(size_t)r * rowstride + segoff + jc_in] = o;
                }
                if (r + 8 < N) {
                    float2 o = make_float2(c[mt][nt][2] + b0, c[mt][nt][3] + b1);
                    *(float2*)&fdst[(size_t)(r + 8) * rowstride + segoff + jc_in] = o;
                }
            }
        }
    }
}

// ---------------- fused pass1: logits + exp + segment-sum z (warp per edge, bf16) ----
__global__ void edge_logits_exp(const int* __restrict__ ei, int E) {
    int w    = (blockIdx.x * blockDim.x + threadIdx.x) >> 5;
    int lane = threadIdx.x & 31;
    if (w >= E) return;
    int src = ei[w], dst = ei[E + w];
    const uint4* qd = (const uint4*)&g_qb[(size_t)dst * QK];
    const uint4* ks = (const uint4*)&g_kb[(size_t)src * QK];
    uint4 a = qd[lane];
    uint4 b = ks[lane];
    float p = dot2bf(a.x, b.x) + dot2bf(a.y, b.y) + dot2bf(a.z, b.z) + dot2bf(a.w, b.w);
    p += __shfl_xor_sync(0xffffffffu, p, 1);
    p += __shfl_xor_sync(0xffffffffu, p, 2);
    p += __shfl_xor_sync(0xffffffffu, p, 4);
    // heads at lanes 0, 8, 16, 24
    float p1 = __shfl_sync(0xffffffffu, p, 8);
    float p2 = __shfl_sync(0xffffffffu, p, 16);
    float p3 = __shfl_sync(0xffffffffu, p, 24);
    if (lane == 0) {
        float4 e4;
        e4.x = __expf(p  * 0.125f);
        e4.y = __expf(p1 * 0.125f);
        e4.z = __expf(p2 * 0.125f);
        e4.w = __expf(p3 * 0.125f);
        *(float4*)&g_sew[(size_t)w * 4] = e4;
        red_add_v4(&g_z[(size_t)dst * 4], e4.x, e4.y, e4.z, e4.w);
    }
}

// ---------------- pass3 (head-mean folded): agg64[dst] += sum_h (alpha_h/4)*v[src][h] ----
__global__ void edge_agg(const int* __restrict__ ei, int E) {
    int gid  = blockIdx.x * blockDim.x + threadIdx.x;
    int e    = gid >> 4;
    int l    = gid & 15;
    if (e >= E) return;
    int src = ei[e], dst = ei[E + e];
    float4 ev = *(const float4*)&g_sew[(size_t)e * 4];
    float4 zz = *(const float4*)&g_z[(size_t)dst * 4];
    float w0 = 0.25f * ev.x / zz.x;
    float w1 = 0.25f * ev.y / zz.y;
    float w2 = 0.25f * ev.z / zz.z;
    float w3 = 0.25f * ev.w / zz.w;
    const float* vb = &g_v[(size_t)src * QK + l * 4];
    float4 a = *(const float4*)(vb);
    float4 b = *(const float4*)(vb + 64);
    float4 c = *(const float4*)(vb + 128);
    float4 d = *(const float4*)(vb + 192);
    float o0 = w0 * a.x + w1 * b.x + w2 * c.x + w3 * d.x;
    float o1 = w0 * a.y + w1 * b.y + w2 * c.y + w3 * d.y;
    float o2 = w0 * a.z + w1 * b.z + w2 * c.z + w3 * d.z;
    float o3 = w0 * a.w + w1 * b.w + w2 * c.w + w3 * d.w;
    red_add_v4(&g_agg[(size_t)dst * HID + l * 4], o0, o1, o2, o3);
}

// ---------------- finalize: relu(agg + skip) ----------------
__global__ void finalize_conv(float* __restrict__ out, int N) {
    int idx = blockIdx.x * blockDim.x + threadIdx.x;   // over N*16 float4s
    if (idx >= N * (HID / 4)) return;
    float4 ag = *(const float4*)&g_agg[(size_t)idx * 4];
    float4 sk = *(const float4*)&g_skip[(size_t)idx * 4];
    float4 o;
    o.x = fmaxf(ag.x + sk.x, 0.f);
    o.y = fmaxf(ag.y + sk.y, 0.f);
    o.z = fmaxf(ag.z + sk.z, 0.f);
    o.w = fmaxf(ag.w + sk.w, 0.f);
    *(float4*)&out[(size_t)idx * 4] = o;
}

// ---------------- pool: per-graph mean of g_h2 (batch is sorted), 64 nodes/block ------
__global__ void pool_kernel(const int* __restrict__ batch, int N) {
    const int NPB = 64;
    int d = threadIdx.x;           // 0..63
    int n0 = blockIdx.x * NPB;
    int n1 = min(n0 + NPB, N);
    float acc = 0.f, cnt = 0.f;
    int cur = -1;
    for (int n = n0; n < n1; n++) {
        int g = batch[n];
        if (g != cur) {
            if (cur >= 0) {
                atomicAdd(&g_gsum[cur * HID + d], acc);
                if (d == 0) atomicAdd(&g_gcnt[cur], cnt);
            }
            cur = g; acc = 0.f; cnt = 0.f;
        }
        acc += g_h2[(size_t)n * HID + d];
        cnt += 1.f;
    }
    if (cur >= 0) {
        atomicAdd(&g_gsum[cur * HID + d], acc);
        if (d == 0) atomicAdd(&g_gcnt[cur], cnt);
    }
}

// ---------------- head: one block per graph; all MLP stages local -------------------
__global__ void __launch_bounds__(128, 8) head_kernel(
        const float* __restrict__ gf,
        const float* __restrict__ gW1, const float* __restrict__ gb1,
        const float* __restrict__ gW2, const float* __restrict__ gb2,
        const float* __restrict__ hW1, const float* __restrict__ hb1,
        const float* __restrict__ hW2, const float* __restrict__ hb2,
        float* __restrict__ out) {
    __shared__ float s_gf[GDIM];
    __shared__ float s_patch[HID];
    __shared__ float s_g1[HID];
    __shared__ float s_g2[HID];
    __shared__ float s_hid[HID];
    int g = blockIdx.x;
    int t = threadIdx.x;

    // stage 0: load gf row + patch embedding
    for (int i = t; i < GDIM; i += 128) s_gf[i] = gf[g * GDIM + i];
    if (t < HID) s_patch[t] = g_gsum[g * HID + t] / fmaxf(g_gcnt[g], 1.f);
    __syncthreads();

    // stage 1: g1 = relu(gf @ gW1 + gb1), K=256 — 2 threads per output (halves of K)
    {
        int j = t >> 1, half = t & 1;
        float s = 0.f;
        int kb = half * 128;
        #pragma unroll 8
        for (int k = 0; k < 128; k++) s += s_gf[kb + k] * gW1[(kb + k) * HID + j];
        s += __shfl_xor_sync(0xffffffffu, s, 1);
        if (half == 0) s_g1[j] = fmaxf(s + gb1[j], 0.f);
    }
    __syncthreads();

    // stage 2: g2 = relu(g1 @ gW2 + gb2), K=64
    if (t < HID) {
        float s = gb2[t];
        #pragma unroll 8
        for (int k = 0; k < HID; k++) s += s_g1[k] * gW2[k * HID + t];
        s_g2[t] = fmaxf(s, 0.f);
    }
    __syncthreads();

    // stage 3: hid = relu([patch, g2] @ hW1 + hb1), K=128 — 2 threads per output
    {
        int j = t >> 1, half = t & 1;
        float s = 0.f;
        const float* src = half ? s_g2 : s_patch;
        int kb = half * HID;
        #pragma unroll 8
        for (int k = 0; k < HID; k++) s += src[k] * hW1[(kb + k) * HID + j];
        s += __shfl_xor_sync(0xffffffffu, s, 1);
        if (half == 0) s_hid[j] = fmaxf(s + hb1[j], 0.f);
    }
    __syncthreads();

    // stage 4: out = hid @ hW2 + hb2  [10]
    if (t < NCLS) {
        float s = hb2[t];
        #pragma unroll 8
        for (int k = 0; k < HID; k++) s += s_hid[k] * hW2[k * NCLS + t];
        out[g * NCLS + t] = s;
    }
}

// ---------------- host orchestration ----------------
static void run_conv(const float* xin, int K, int N, int E, const int* ei,
                     const float* Wq, const float* bq, const float* Wk, const float* bk,
                     const float* Wv, const float* bv, const float* Ws, const float* bs,
                     float* hout, void* z_p, void* agg_p) {
    pack_w<<<(K * OCT + 255) / 256, 256>>>(Wq, bq, Wk, bk, Wv, bv, Ws, bs, K);
    cudaMemsetAsync(z_p,   0, (size_t)N * HEADS * sizeof(float), 0);
    cudaMemsetAsync(agg_p, 0, (size_t)N * HID * sizeof(float), 0);
    dim3 gg((N + 127) / 128, OCT / 64);
    gemm_qkvs<<<gg, 256>>>(xin, N, K);
    int lthreads = E * 32;
    edge_logits_exp<<<(lthreads + 255) / 256, 256>>>(ei, E);
    int athreads = E * 16;
    edge_agg<<<(athreads + 255) / 256, 256>>>(ei, E);
    finalize_conv<<<(N * (HID / 4) + 255) / 256, 256>>>(hout, N);
}

extern "C" void kernel_launch(void* const* d_in, const int* in_sizes, int n_in,
                              void* d_out, int out_size) {
    const float* x     = (const float*)d_in[0];
    const int*   ei    = (const int*)  d_in[1];
    const int*   batch = (const int*)  d_in[2];
    const float* gf    = (const float*)d_in[3];
    const float* c1[8]; for (int i = 0; i < 8; i++) c1[i] = (const float*)d_in[4 + i];
    const float* c2[8]; for (int i = 0; i < 8; i++) c2[i] = (const float*)d_in[12 + i];
    const float* gW1 = (const float*)d_in[20]; const float* gb1 = (const float*)d_in[21];
    const float* gW2 = (const float*)d_in[22]; const float* gb2 = (const float*)d_in[23];
    const float* hW1 = (const float*)d_in[24]; const float* hb1 = (const float*)d_in[25];
    const float* hW2 = (const float*)d_in[26]; const float* hb2 = (const float*)d_in[27];

    int N = in_sizes[0] / 128;
    int E = in_sizes[1] / 2;

    void *p_h1, *p_h2, *p_z, *p_agg, *p_gsum, *p_gcnt;
    cudaGetSymbolAddress(&p_h1,   g_h1);
    cudaGetSymbolAddress(&p_h2,   g_h2);
    cudaGetSymbolAddress(&p_z,    g_z);
    cudaGetSymbolAddress(&p_agg,  g_agg);
    cudaGetSymbolAddress(&p_gsum, g_gsum);
    cudaGetSymbolAddress(&p_gcnt, g_gcnt);

    // conv1 (in=128)
    run_conv(x, 128, N, E, ei,
             c1[0], c1[1], c1[2], c1[3], c1[4], c1[5], c1[6], c1[7],
             (float*)p_h1, p_z, p_agg);
    // conv2 (in=64)
    run_conv((const float*)p_h1, 64, N, E, ei,
             c2[0], c2[1], c2[2], c2[3], c2[4], c2[5], c2[6], c2[7],
             (float*)p_h2, p_z, p_agg);

    // pooling
    cudaMemsetAsync(p_gsum, 0, NGRAPH * HID * sizeof(float), 0);
    cudaMemsetAsync(p_gcnt, 0, NGRAPH * sizeof(float), 0);
    pool_kernel<<<(N + 63) / 64, HID>>>(batch, N);

    // head (one block per graph)
    head_kernel<<<NGRAPH, 128>>>(gf, gW1, gb1, gW2, gb2, hW1, hb1, hW2, hb2, (float*)d_out);
}

// round 9
// speedup vs baseline: 1.8714x; 1.0336x over previous
#include <cuda_runtime.h>
#include <cuda_bf16.h>
#include <math.h>
#include <cstdint>

// Problem constants
#define NMAX   50000
#define EMAX   800000
#define HEADS  4
#define HID    64
#define QK     256        // HEADS*HID
#define OCT    832        // 3*QK + HID
#define NGRAPH 64
#define GDIM   256
#define NCLS   10

// ---------------- scratch (device globals; no runtime allocation) ----------------
__device__ __align__(16) __nv_bfloat16 g_qb[NMAX * QK];   // bf16 q (logits only)
__device__ __align__(16) __nv_bfloat16 g_kb[NMAX * QK];   // bf16 k (logits only)
__device__ __align__(16) __nv_bfloat16 g_vb[NMAX * QK];   // bf16 v (agg only)
__device__ __align__(16) float    g_skip[NMAX * HID];
__device__ __align__(16) float    g_agg [NMAX * HID];   // head-mean folded
__device__ __align__(16) float    g_h1  [NMAX * HID];
__device__ __align__(16) float    g_h2  [NMAX * HID];
__device__ __align__(16) float    g_sew [EMAX * HEADS];
__device__ __align__(16) float    g_z   [NMAX * HEADS];
__device__ __align__(16) float    g_Wc  [128 * OCT];
__device__ __align__(16) float    g_bc  [OCT];
__device__ __align__(16) float    g_gsum[NGRAPH * HID];
__device__ __align__(16) float    g_gcnt[NGRAPH];

// ---------------- helpers ----------------
__device__ __forceinline__ void red_add_v4(float* p, float a, float b, float c, float d) {
    asm volatile("red.global.add.v4.f32 [%0], {%1,%2,%3,%4};"
                 :: "l"(p), "f"(a), "f"(b), "f"(c), "f"(d) : "memory");
}
// pack two fp32 into one uint32 of two bf16 (lo half = first)
__device__ __forceinline__ uint32_t pack_bf16(float a, float b) {
    __nv_bfloat16 ha = __float2bfloat16_rn(a);
    __nv_bfloat16 hb = __float2bfloat16_rn(b);
    return (uint32_t)__bfloat16_as_ushort(ha) | ((uint32_t)__bfloat16_as_ushort(hb) << 16);
}
__device__ __forceinline__ float bf_hi_res(float v) {   // v - bf16(v)
    return v - __bfloat162float(__float2bfloat16_rn(v));
}
__device__ __forceinline__ float bflo(uint32_t u) { return __uint_as_float(u << 16); }
__device__ __forceinline__ float bfhi(uint32_t u) { return __uint_as_float(u & 0xffff0000u); }
// dot of 2 bf16 pairs packed as uint32
__device__ __forceinline__ float dot2bf(uint32_t ua, uint32_t ub) {
    return bflo(ua) * bflo(ub) + bfhi(ua) * bfhi(ub);
}

#define MMA_BF16(c, a, b)                                                     \
    asm volatile("mma.sync.aligned.m16n8k16.row.col.f32.bf16.bf16.f32 "       \
                 "{%0,%1,%2,%3}, {%4,%5,%6,%7}, {%8,%9}, {%0,%1,%2,%3};"      \
                 : "+f"((c)[0]), "+f"((c)[1]), "+f"((c)[2]), "+f"((c)[3])     \
                 : "r"((a)[0]), "r"((a)[1]), "r"((a)[2]), "r"((a)[3]),        \
                   "r"((b)[0]), "r"((b)[1]))

// ---------------- weight pack: Wc[K][832] = [Wq|Wk|Wv|Ws], bc[832] ----------------
__global__ void pack_w(const float* __restrict__ Wq, const float* __restrict__ bq,
                       const float* __restrict__ Wk, const float* __restrict__ bk,
                       const float* __restrict__ Wv, const float* __restrict__ bv,
                       const float* __restrict__ Ws, const float* __restrict__ bs, int K) {
    int idx = blockIdx.x * blockDim.x + threadIdx.x;
    int tot = K * OCT;
    if (idx < tot) {
        int k = idx / OCT, j = idx - k * OCT;
        float v;
        if      (j < 256) v = Wq[k * 256 + j];
        else if (j < 512) v = Wk[k * 256 + (j - 256)];
        else if (j < 768) v = Wv[k * 256 + (j - 512)];
        else              v = Ws[k * 64  + (j - 768)];
        g_Wc[idx] = v;
    }
    if (idx < OCT) {
        float b;
        if      (idx < 256) b = bq[idx];
        else if (idx < 512) b = bk[idx - 256];
        else if (idx < 768) b = bv[idx - 512];
        else                b = bs[idx - 768];
        g_bc[idx] = b;
    }
}

// ---------------- GEMM: C[N,832] = A[N,K] @ Wc[K,832] + bc ; routed to q/k/v/skip ----
// 3xBF16-split tensor-core GEMM via mma.sync.m16n8k16. q,k,v stored as bf16.
#define ASTR32 136
#define BSTR32 72
__global__ void __launch_bounds__(256, 2) gemm_qkvs(const float* __restrict__ A, int N, int K) {
    __shared__ uint32_t As[2][8 * ASTR32];   // [hi/lo][kpair][m]
    __shared__ uint32_t Bs[2][8 * BSTR32];   // [hi/lo][kpair][n]
    const int t    = threadIdx.x;
    const int lane = t & 31, wid = t >> 5;
    const int warp_m = wid & 3;          // 0..3 -> 32-row slab
    const int warp_n = wid >> 2;         // 0..1 -> 32-col slab
    const int row0 = blockIdx.x * 128, col0 = blockIdx.y * 64;
    const int lq = lane >> 2;            // 0..7
    const int lr = lane & 3;             // 0..3

    float c[2][4][4];
    #pragma unroll
    for (int mt = 0; mt < 2; mt++)
        #pragma unroll
        for (int nt = 0; nt < 4; nt++)
            #pragma unroll
            for (int i = 0; i < 4; i++) c[mt][nt][i] = 0.f;

    for (int k0 = 0; k0 < K; k0 += 16) {
        // --- stage A 128x16 -> As[hi/lo][kp][m] packed k-pairs ---
        #pragma unroll
        for (int ii = 0; ii < 2; ii++) {
            int idx = t + ii * 256;
            int r = idx >> 2, cg = (idx & 3) << 2;   // cg in {0,4,8,12}
            int gr = row0 + r;
            float4 a = (gr < N) ? *(const float4*)&A[(size_t)gr * K + k0 + cg]
                                : make_float4(0.f, 0.f, 0.f, 0.f);
            int kp = cg >> 1;
            As[0][kp * ASTR32 + r]       = pack_bf16(a.x, a.y);
            As[0][(kp + 1) * ASTR32 + r] = pack_bf16(a.z, a.w);
            As[1][kp * ASTR32 + r]       = pack_bf16(bf_hi_res(a.x), bf_hi_res(a.y));
            As[1][(kp + 1) * ASTR32 + r] = pack_bf16(bf_hi_res(a.z), bf_hi_res(a.w));
        }
        // --- stage B 16x64 -> Bs[hi/lo][kp][n] packed over k ---
        if (t < 128) {
            int kp = t >> 4, j4 = (t & 15) << 2;
            const float* r0p = &g_Wc[(size_t)(k0 + 2 * kp) * OCT + col0 + j4];
            const float* r1p = r0p + OCT;
            float4 b0 = *(const float4*)r0p;
            float4 b1 = *(const float4*)r1p;
            float v0[4] = {b0.x, b0.y, b0.z, b0.w};
            float v1[4] = {b1.x, b1.y, b1.z, b1.w};
            #pragma unroll
            for (int i = 0; i < 4; i++) {
                Bs[0][kp * BSTR32 + j4 + i] = pack_bf16(v0[i], v1[i]);
                Bs[1][kp * BSTR32 + j4 + i] = pack_bf16(bf_hi_res(v0[i]), bf_hi_res(v1[i]));
            }
        }
        __syncthreads();

        // --- fragments + MMAs (one k16 step per tile) ---
        uint32_t ah[2][4], al[2][4];
        #pragma unroll
        for (int mt = 0; mt < 2; mt++) {
            int r0 = warp_m * 32 + mt * 16 + lq;
            ah[mt][0] = As[0][lr * ASTR32 + r0];
            ah[mt][1] = As[0][lr * ASTR32 + r0 + 8];
            ah[mt][2] = As[0][(lr + 4) * ASTR32 + r0];
            ah[mt][3] = As[0][(lr + 4) * ASTR32 + r0 + 8];
            al[mt][0] = As[1][lr * ASTR32 + r0];
            al[mt][1] = As[1][lr * ASTR32 + r0 + 8];
            al[mt][2] = As[1][(lr + 4) * ASTR32 + r0];
            al[mt][3] = As[1][(lr + 4) * ASTR32 + r0 + 8];
        }
        uint32_t bh[4][2], bl[4][2];
        #pragma unroll
        for (int nt = 0; nt < 4; nt++) {
            int n = warp_n * 32 + nt * 8 + lq;
            bh[nt][0] = Bs[0][lr * BSTR32 + n];
            bh[nt][1] = Bs[0][(lr + 4) * BSTR32 + n];
            bl[nt][0] = Bs[1][lr * BSTR32 + n];
            bl[nt][1] = Bs[1][(lr + 4) * BSTR32 + n];
        }
        #pragma unroll
        for (int mt = 0; mt < 2; mt++)
            #pragma unroll
            for (int nt = 0; nt < 4; nt++) {
                MMA_BF16(c[mt][nt], ah[mt], bh[nt]);
                MMA_BF16(c[mt][nt], al[mt], bh[nt]);
                MMA_BF16(c[mt][nt], ah[mt], bl[nt]);
            }
        __syncthreads();
    }

    // --- epilogue: q/k/v -> bf16 packed; skip -> fp32 ---
    int y = blockIdx.y;
    bool is_bf = (y < 12);
    __nv_bfloat16* bfdst; int bfoff;
    if      (y < 4) { bfdst = g_qb; bfoff = col0;       }
    else if (y < 8) { bfdst = g_kb; bfoff = col0 - 256; }
    else            { bfdst = g_vb; bfoff = col0 - 512; }

    #pragma unroll
    for (int mt = 0; mt < 2; mt++) {
        int r = row0 + warp_m * 32 + mt * 16 + lq;
        #pragma unroll
        for (int nt = 0; nt < 4; nt++) {
            int jc_in = warp_n * 32 + nt * 8 + lr * 2;   // in-block col (even)
            float b0 = g_bc[col0 + jc_in];
            float b1 = g_bc[col0 + jc_in + 1];
            if (is_bf) {
                if (r < N) {
                    *(uint32_t*)&bfdst[(size_t)r * 256 + bfoff + jc_in] =
                        pack_bf16(c[mt][nt][0] + b0, c[mt][nt][1] + b1);
                }
                if (r + 8 < N) {
                    *(uint32_t*)&bfdst[(size_t)(r + 8) * 256 + bfoff + jc_in] =
                        pack_bf16(c[mt][nt][2] + b0, c[mt][nt][3] + b1);
                }
            } else {
                if (r < N) {
                    float2 o = make_float2(c[mt][nt][0] + b0, c[mt][nt][1] + b1);
                    *(float2*)&g_skip[(size_t)r * 64 + jc_in] = o;
                }
                if (r + 8 < N) {
                    float2 o = make_float2(c[mt][nt][2] + b0, c[mt][nt][3] + b1);
                    *(float2*)&g_skip[(size_t)(r + 8) * 64 + jc_in] = o;
                }
            }
        }
    }
}

// ---------------- fused pass1: logits + exp + segment-sum z (warp per edge, bf16) ----
__global__ void edge_logits_exp(const int* __restrict__ ei, int E) {
    int w    = (blockIdx.x * blockDim.x + threadIdx.x) >> 5;
    int lane = threadIdx.x & 31;
    if (w >= E) return;
    int src = ei[w], dst = ei[E + w];
    const uint4* qd = (const uint4*)&g_qb[(size_t)dst * QK];
    const uint4* ks = (const uint4*)&g_kb[(size_t)src * QK];
    uint4 a = qd[lane];
    uint4 b = ks[lane];
    float p = dot2bf(a.x, b.x) + dot2bf(a.y, b.y) + dot2bf(a.z, b.z) + dot2bf(a.w, b.w);
    p += __shfl_xor_sync(0xffffffffu, p, 1);
    p += __shfl_xor_sync(0xffffffffu, p, 2);
    p += __shfl_xor_sync(0xffffffffu, p, 4);
    // heads at lanes 0, 8, 16, 24
    float p1 = __shfl_sync(0xffffffffu, p, 8);
    float p2 = __shfl_sync(0xffffffffu, p, 16);
    float p3 = __shfl_sync(0xffffffffu, p, 24);
    if (lane == 0) {
        float4 e4;
        e4.x = __expf(p  * 0.125f);
        e4.y = __expf(p1 * 0.125f);
        e4.z = __expf(p2 * 0.125f);
        e4.w = __expf(p3 * 0.125f);
        *(float4*)&g_sew[(size_t)w * 4] = e4;
        red_add_v4(&g_z[(size_t)dst * 4], e4.x, e4.y, e4.z, e4.w);
    }
}

// ---------------- pass3 (head-mean folded): agg64[dst] += sum_h (alpha_h/4)*v[src][h] ----
// 8 lanes per edge; each lane owns 8 output dims; v is bf16 (uint4 = 8 elems).
__global__ void edge_agg(const int* __restrict__ ei, int E) {
    int gid = blockIdx.x * blockDim.x + threadIdx.x;
    int e   = gid >> 3;
    int l   = gid & 7;
    if (e >= E) return;
    int src = ei[e], dst = ei[E + e];
    float4 ev = *(const float4*)&g_sew[(size_t)e * 4];
    float4 zz = *(const float4*)&g_z[(size_t)dst * 4];
    float w0 = 0.25f * ev.x / zz.x;
    float w1 = 0.25f * ev.y / zz.y;
    float w2 = 0.25f * ev.z / zz.z;
    float w3 = 0.25f * ev.w / zz.w;
    const uint4* vb = (const uint4*)&g_vb[(size_t)src * QK];   // 32 uint4 per node
    uint4 a = vb[l];          // head 0, dims l*8..l*8+7
    uint4 b = vb[8 + l];      // head 1
    uint4 c = vb[16 + l];     // head 2
    uint4 d = vb[24 + l];     // head 3
    float o[8];
    const uint32_t* ua = (const uint32_t*)&a;
    const uint32_t* ub = (const uint32_t*)&b;
    const uint32_t* uc = (const uint32_t*)&c;
    const uint32_t* ud = (const uint32_t*)&d;
    #pragma unroll
    for (int i = 0; i < 4; i++) {
        o[2 * i]     = w0 * bflo(ua[i]) + w1 * bflo(ub[i]) + w2 * bflo(uc[i]) + w3 * bflo(ud[i]);
        o[2 * i + 1] = w0 * bfhi(ua[i]) + w1 * bfhi(ub[i]) + w2 * bfhi(uc[i]) + w3 * bfhi(ud[i]);
    }
    float* ap = &g_agg[(size_t)dst * HID + l * 8];
    red_add_v4(ap,     o[0], o[1], o[2], o[3]);
    red_add_v4(ap + 4, o[4], o[5], o[6], o[7]);
}

// ---------------- finalize: relu(agg + skip) ----------------
__global__ void finalize_conv(float* __restrict__ out, int N) {
    int idx = blockIdx.x * blockDim.x + threadIdx.x;   // over N*16 float4s
    if (idx >= N * (HID / 4)) return;
    float4 ag = *(const float4*)&g_agg[(size_t)idx * 4];
    float4 sk = *(const float4*)&g_skip[(size_t)idx * 4];
    float4 o;
    o.x = fmaxf(ag.x + sk.x, 0.f);
    o.y = fmaxf(ag.y + sk.y, 0.f);
    o.z = fmaxf(ag.z + sk.z, 0.f);
    o.w = fmaxf(ag.w + sk.w, 0.f);
    *(float4*)&out[(size_t)idx * 4] = o;
}

// ---------------- pool: per-graph mean of g_h2 (batch is sorted), 64 nodes/block ------
__global__ void pool_kernel(const int* __restrict__ batch, int N) {
    const int NPB = 64;
    int d = threadIdx.x;           // 0..63
    int n0 = blockIdx.x * NPB;
    int n1 = min(n0 + NPB, N);
    float acc = 0.f, cnt = 0.f;
    int cur = -1;
    for (int n = n0; n < n1; n++) {
        int g = batch[n];
        if (g != cur) {
            if (cur >= 0) {
                atomicAdd(&g_gsum[cur * HID + d], acc);
                if (d == 0) atomicAdd(&g_gcnt[cur], cnt);
            }
            cur = g; acc = 0.f; cnt = 0.f;
        }
        acc += g_h2[(size_t)n * HID + d];
        cnt += 1.f;
    }
    if (cur >= 0) {
        atomicAdd(&g_gsum[cur * HID + d], acc);
        if (d == 0) atomicAdd(&g_gcnt[cur], cnt);
    }
}

// ---------------- head: one block per graph; all MLP stages local -------------------
__global__ void __launch_bounds__(128, 8) head_kernel(
        const float* __restrict__ gf,
        const float* __restrict__ gW1, const float* __restrict__ gb1,
        const float* __restrict__ gW2, const float* __restrict__ gb2,
        const float* __restrict__ hW1, const float* __restrict__ hb1,
        const float* __restrict__ hW2, const float* __restrict__ hb2,
        float* __restrict__ out) {
    __shared__ float s_gf[GDIM];
    __shared__ float s_patch[HID];
    __shared__ float s_g1[HID];
    __shared__ float s_g2[HID];
    __shared__ float s_hid[HID];
    int g = blockIdx.x;
    int t = threadIdx.x;

    for (int i = t; i < GDIM; i += 128) s_gf[i] = gf[g * GDIM + i];
    if (t < HID) s_patch[t] = g_gsum[g * HID + t] / fmaxf(g_gcnt[g], 1.f);
    __syncthreads();

    // stage 1: g1 = relu(gf @ gW1 + gb1), K=256 — 2 threads per output
    {
        int j = t >> 1, half = t & 1;
        float s = 0.f;
        int kb = half * 128;
        #pragma unroll 8
        for (int k = 0; k < 128; k++) s += s_gf[kb + k] * gW1[(kb + k) * HID + j];
        s += __shfl_xor_sync(0xffffffffu, s, 1);
        if (half == 0) s_g1[j] = fmaxf(s + gb1[j], 0.f);
    }
    __syncthreads();

    // stage 2: g2 = relu(g1 @ gW2 + gb2), K=64
    if (t < HID) {
        float s = gb2[t];
        #pragma unroll 8
        for (int k = 0; k < HID; k++) s += s_g1[k] * gW2[k * HID + t];
        s_g2[t] = fmaxf(s, 0.f);
    }
    __syncthreads();

    // stage 3: hid = relu([patch, g2] @ hW1 + hb1), K=128 — 2 threads per output
    {
        int j = t >> 1, half = t & 1;
        float s = 0.f;
        const float* src = half ? s_g2 : s_patch;
        int kb = half * HID;
        #pragma unroll 8
        for (int k = 0; k < HID; k++) s += src[k] * hW1[(kb + k) * HID + j];
        s += __shfl_xor_sync(0xffffffffu, s, 1);
        if (half == 0) s_hid[j] = fmaxf(s + hb1[j], 0.f);
    }
    __syncthreads();

    // stage 4: out = hid @ hW2 + hb2  [10]
    if (t < NCLS) {
        float s = hb2[t];
        #pragma unroll 8
        for (int k = 0; k < HID; k++) s += s_hid[k] * hW2[k * NCLS + t];
        out[g * NCLS + t] = s;
    }
}

// ---------------- host orchestration ----------------
static void run_conv(const float* xin, int K, int N, int E, const int* ei,
                     const float* Wq, const float* bq, const float* Wk, const float* bk,
                     const float* Wv, const float* bv, const float* Ws, const float* bs,
                     float* hout, void* z_p, void* agg_p) {
    pack_w<<<(K * OCT + 255) / 256, 256>>>(Wq, bq, Wk, bk, Wv, bv, Ws, bs, K);
    cudaMemsetAsync(z_p,   0, (size_t)N * HEADS * sizeof(float), 0);
    cudaMemsetAsync(agg_p, 0, (size_t)N * HID * sizeof(float), 0);
    dim3 gg((N + 127) / 128, OCT / 64);
    gemm_qkvs<<<gg, 256>>>(xin, N, K);
    int lthreads = E * 32;
    edge_logits_exp<<<(lthreads + 255) / 256, 256>>>(ei, E);
    int athreads = E * 8;
    edge_agg<<<(athreads + 255) / 256, 256>>>(ei, E);
    finalize_conv<<<(N * (HID / 4) + 255) / 256, 256>>>(hout, N);
}

extern "C" void kernel_launch(void* const* d_in, const int* in_sizes, int n_in,
                              void* d_out, int out_size) {
    const float* x     = (const float*)d_in[0];
    const int*   ei    = (const int*)  d_in[1];
    const int*   batch = (const int*)  d_in[2];
    const float* gf    = (const float*)d_in[3];
    const float* c1[8]; for (int i = 0; i < 8; i++) c1[i] = (const float*)d_in[4 + i];
    const float* c2[8]; for (int i = 0; i < 8; i++) c2[i] = (const float*)d_in[12 + i];
    const float* gW1 = (const float*)d_in[20]; const float* gb1 = (const float*)d_in[21];
    const float* gW2 = (const float*)d_in[22]; const float* gb2 = (const float*)d_in[23];
    const float* hW1 = (const float*)d_in[24]; const float* hb1 = (const float*)d_in[25];
    const float* hW2 = (const float*)d_in[26]; const float* hb2 = (const float*)d_in[27];

    int N = in_sizes[0] / 128;
    int E = in_sizes[1] / 2;

    void *p_h1, *p_h2, *p_z, *p_agg, *p_gsum, *p_gcnt;
    cudaGetSymbolAddress(&p_h1,   g_h1);
    cudaGetSymbolAddress(&p_h2,   g_h2);
    cudaGetSymbolAddress(&p_z,    g_z);
    cudaGetSymbolAddress(&p_agg,  g_agg);
    cudaGetSymbolAddress(&p_gsum, g_gsum);
    cudaGetSymbolAddress(&p_gcnt, g_gcnt);

    // conv1 (in=128)
    run_conv(x, 128, N, E, ei,
             c1[0], c1[1], c1[2], c1[3], c1[4], c1[5], c1[6], c1[7],
             (float*)p_h1, p_z, p_agg);
    // conv2 (in=64)
    run_conv((const float*)p_h1, 64, N, E, ei,
             c2[0], c2[1], c2[2], c2[3], c2[4], c2[5], c2[6], c2[7],
             (float*)p_h2, p_z, p_agg);

    // pooling
    cudaMemsetAsync(p_gsum, 0, NGRAPH * HID * sizeof(float), 0);
    cudaMemsetAsync(p_gcnt, 0, NGRAPH * sizeof(float), 0);
    pool_kernel<<<(N + 63) / 64, HID>>>(batch, N);

    // head (one block per graph)
    head_kernel<<<NGRAPH, 128>>>(gf, gW1, gb1, gW2, gb2, hW1, hb1, hW2, hb2, (float*)d_out);
}

// round 10
// speedup vs baseline: 2.0028x; 1.0702x over previous
#include <cuda_runtime.h>
#include <cuda_bf16.h>
#include <math.h>
#include <cstdint>

// Problem constants
#define NMAX   50000
#define EMAX   800000
#define HEADS  4
#define HID    64
#define QK     256        // HEADS*HID
#define OCT    832        // 3*QK + HID
#define NGRAPH 64
#define GDIM   256
#define NCLS   10

// ---------------- scratch (device globals; no runtime allocation) ----------------
__device__ __align__(16) __nv_bfloat16 g_qb[NMAX * QK];   // bf16 q
__device__ __align__(16) __nv_bfloat16 g_kb[NMAX * QK];   // bf16 k
__device__ __align__(16) __nv_bfloat16 g_vb[NMAX * QK];   // bf16 v
__device__ __align__(16) float    g_skip[NMAX * HID];
__device__ __align__(16) float    g_h1  [NMAX * HID];
__device__ __align__(16) float    g_h2  [NMAX * HID];
__device__ __align__(16) float    g_Wc  [128 * OCT];
__device__ __align__(16) float    g_bc  [OCT];
__device__ __align__(16) float    g_gsum[NGRAPH * HID];
__device__ __align__(16) float    g_gcnt[NGRAPH];
// CSR (dst-sorted) graph, built once per launch
__device__ __align__(16) int      g_rowptr[NMAX + 1];
__device__ __align__(16) int      g_cursor[NMAX];
__device__ __align__(16) int      g_srcs  [EMAX];

// ---------------- helpers ----------------
__device__ __forceinline__ uint32_t pack_bf16(float a, float b) {
    __nv_bfloat16 ha = __float2bfloat16_rn(a);
    __nv_bfloat16 hb = __float2bfloat16_rn(b);
    return (uint32_t)__bfloat16_as_ushort(ha) | ((uint32_t)__bfloat16_as_ushort(hb) << 16);
}
__device__ __forceinline__ float bf_hi_res(float v) {   // v - bf16(v)
    return v - __bfloat162float(__float2bfloat16_rn(v));
}
__device__ __forceinline__ float bflo(uint32_t u) { return __uint_as_float(u << 16); }
__device__ __forceinline__ float bfhi(uint32_t u) { return __uint_as_float(u & 0xffff0000u); }
__device__ __forceinline__ float dot2bf(uint32_t ua, uint32_t ub) {
    return bflo(ua) * bflo(ub) + bfhi(ua) * bfhi(ub);
}

#define MMA_BF16(c, a, b)                                                     \
    asm volatile("mma.sync.aligned.m16n8k16.row.col.f32.bf16.bf16.f32 "       \
                 "{%0,%1,%2,%3}, {%4,%5,%6,%7}, {%8,%9}, {%0,%1,%2,%3};"      \
                 : "+f"((c)[0]), "+f"((c)[1]), "+f"((c)[2]), "+f"((c)[3])     \
                 : "r"((a)[0]), "r"((a)[1]), "r"((a)[2]), "r"((a)[3]),        \
                   "r"((b)[0]), "r"((b)[1]))

// ---------------- CSR build ----------------
__global__ void hist_kernel(const int* __restrict__ ei, int E) {
    int e = blockIdx.x * blockDim.x + threadIdx.x;
    if (e < E) atomicAdd(&g_cursor[ei[E + e]], 1);
}
// single block, 1024 threads: exclusive scan of counts -> rowptr & cursor
__global__ void scan_kernel(int N, int E) {
    __shared__ int s_part[1024];
    int t = threadIdx.x;
    int chunk = (N + 1023) >> 10;
    int b = t * chunk, en = min(b + chunk, N);
    int sum = 0;
    for (int i = b; i < en; i++) sum += g_cursor[i];
    s_part[t] = sum;
    __syncthreads();
    // inclusive Hillis-Steele
    for (int off = 1; off < 1024; off <<= 1) {
        int v = (t >= off) ? s_part[t - off] : 0;
        __syncthreads();
        s_part[t] += v;
        __syncthreads();
    }
    int run = s_part[t] - sum;   // exclusive base
    for (int i = b; i < en; i++) {
        int c = g_cursor[i];
        g_rowptr[i] = run;
        g_cursor[i] = run;
        run += c;
    }
    if (t == 0) g_rowptr[N] = E;
}
__global__ void scatter_kernel(const int* __restrict__ ei, int E) {
    int e = blockIdx.x * blockDim.x + threadIdx.x;
    if (e >= E) return;
    int src = ei[e], dst = ei[E + e];
    int pos = atomicAdd(&g_cursor[dst], 1);
    g_srcs[pos] = src;
}

// ---------------- weight pack ----------------
__global__ void pack_w(const float* __restrict__ Wq, const float* __restrict__ bq,
                       const float* __restrict__ Wk, const float* __restrict__ bk,
                       const float* __restrict__ Wv, const float* __restrict__ bv,
                       const float* __restrict__ Ws, const float* __restrict__ bs, int K) {
    int idx = blockIdx.x * blockDim.x + threadIdx.x;
    int tot = K * OCT;
    if (idx < tot) {
        int k = idx / OCT, j = idx - k * OCT;
        float v;
        if      (j < 256) v = Wq[k * 256 + j];
        else if (j < 512) v = Wk[k * 256 + (j - 256)];
        else if (j < 768) v = Wv[k * 256 + (j - 512)];
        else              v = Ws[k * 64  + (j - 768)];
        g_Wc[idx] = v;
    }
    if (idx < OCT) {
        float b;
        if      (idx < 256) b = bq[idx];
        else if (idx < 512) b = bk[idx - 256];
        else if (idx < 768) b = bv[idx - 512];
        else                b = bs[idx - 768];
        g_bc[idx] = b;
    }
}

// ---------------- GEMM: 3xBF16-split mma.sync.m16n8k16 ----------------
#define ASTR32 136
#define BSTR32 72
__global__ void __launch_bounds__(256, 2) gemm_qkvs(const float* __restrict__ A, int N, int K) {
    __shared__ uint32_t As[2][8 * ASTR32];
    __shared__ uint32_t Bs[2][8 * BSTR32];
    const int t    = threadIdx.x;
    const int lane = t & 31, wid = t >> 5;
    const int warp_m = wid & 3;
    const int warp_n = wid >> 2;
    const int row0 = blockIdx.x * 128, col0 = blockIdx.y * 64;
    const int lq = lane >> 2;
    const int lr = lane & 3;

    float c[2][4][4];
    #pragma unroll
    for (int mt = 0; mt < 2; mt++)
        #pragma unroll
        for (int nt = 0; nt < 4; nt++)
            #pragma unroll
            for (int i = 0; i < 4; i++) c[mt][nt][i] = 0.f;

    for (int k0 = 0; k0 < K; k0 += 16) {
        #pragma unroll
        for (int ii = 0; ii < 2; ii++) {
            int idx = t + ii * 256;
            int r = idx >> 2, cg = (idx & 3) << 2;
            int gr = row0 + r;
            float4 a = (gr < N) ? *(const float4*)&A[(size_t)gr * K + k0 + cg]
                                : make_float4(0.f, 0.f, 0.f, 0.f);
            int kp = cg >> 1;
            As[0][kp * ASTR32 + r]       = pack_bf16(a.x, a.y);
            As[0][(kp + 1) * ASTR32 + r] = pack_bf16(a.z, a.w);
            As[1][kp * ASTR32 + r]       = pack_bf16(bf_hi_res(a.x), bf_hi_res(a.y));
            As[1][(kp + 1) * ASTR32 + r] = pack_bf16(bf_hi_res(a.z), bf_hi_res(a.w));
        }
        if (t < 128) {
            int kp = t >> 4, j4 = (t & 15) << 2;
            const float* r0p = &g_Wc[(size_t)(k0 + 2 * kp) * OCT + col0 + j4];
            const float* r1p = r0p + OCT;
            float4 b0 = *(const float4*)r0p;
            float4 b1 = *(const float4*)r1p;
            float v0[4] = {b0.x, b0.y, b0.z, b0.w};
            float v1[4] = {b1.x, b1.y, b1.z, b1.w};
            #pragma unroll
            for (int i = 0; i < 4; i++) {
                Bs[0][kp * BSTR32 + j4 + i] = pack_bf16(v0[i], v1[i]);
                Bs[1][kp * BSTR32 + j4 + i] = pack_bf16(bf_hi_res(v0[i]), bf_hi_res(v1[i]));
            }
        }
        __syncthreads();

        uint32_t ah[2][4], al[2][4];
        #pragma unroll
        for (int mt = 0; mt < 2; mt++) {
            int r0 = warp_m * 32 + mt * 16 + lq;
            ah[mt][0] = As[0][lr * ASTR32 + r0];
            ah[mt][1] = As[0][lr * ASTR32 + r0 + 8];
            ah[mt][2] = As[0][(lr + 4) * ASTR32 + r0];
            ah[mt][3] = As[0][(lr + 4) * ASTR32 + r0 + 8];
            al[mt][0] = As[1][lr * ASTR32 + r0];
            al[mt][1] = As[1][lr * ASTR32 + r0 + 8];
            al[mt][2] = As[1][(lr + 4) * ASTR32 + r0];
            al[mt][3] = As[1][(lr + 4) * ASTR32 + r0 + 8];
        }
        uint32_t bh[4][2], bl[4][2];
        #pragma unroll
        for (int nt = 0; nt < 4; nt++) {
            int n = warp_n * 32 + nt * 8 + lq;
            bh[nt][0] = Bs[0][lr * BSTR32 + n];
            bh[nt][1] = Bs[0][(lr + 4) * BSTR32 + n];
            bl[nt][0] = Bs[1][lr * BSTR32 + n];
            bl[nt][1] = Bs[1][(lr + 4) * BSTR32 + n];
        }
        #pragma unroll
        for (int mt = 0; mt < 2; mt++)
            #pragma unroll
            for (int nt = 0; nt < 4; nt++) {
                MMA_BF16(c[mt][nt], ah[mt], bh[nt]);
                MMA_BF16(c[mt][nt], al[mt], bh[nt]);
                MMA_BF16(c[mt][nt], ah[mt], bl[nt]);
            }
        __syncthreads();
    }

    int y = blockIdx.y;
    bool is_bf = (y < 12);
    __nv_bfloat16* bfdst; int bfoff;
    if      (y < 4) { bfdst = g_qb; bfoff = col0;       }
    else if (y < 8) { bfdst = g_kb; bfoff = col0 - 256; }
    else            { bfdst = g_vb; bfoff = col0 - 512; }

    #pragma unroll
    for (int mt = 0; mt < 2; mt++) {
        int r = row0 + warp_m * 32 + mt * 16 + lq;
        #pragma unroll
        for (int nt = 0; nt < 4; nt++) {
            int jc_in = warp_n * 32 + nt * 8 + lr * 2;
            float b0 = g_bc[col0 + jc_in];
            float b1 = g_bc[col0 + jc_in + 1];
            if (is_bf) {
                if (r < N) {
                    *(uint32_t*)&bfdst[(size_t)r * 256 + bfoff + jc_in] =
                        pack_bf16(c[mt][nt][0] + b0, c[mt][nt][1] + b1);
                }
                if (r + 8 < N) {
                    *(uint32_t*)&bfdst[(size_t)(r + 8) * 256 + bfoff + jc_in] =
                        pack_bf16(c[mt][nt][2] + b0, c[mt][nt][3] + b1);
                }
            } else {
                if (r < N) {
                    float2 o = make_float2(c[mt][nt][0] + b0, c[mt][nt][1] + b1);
                    *(float2*)&g_skip[(size_t)r * 64 + jc_in] = o;
                }
                if (r + 8 < N) {
                    float2 o = make_float2(c[mt][nt][2] + b0, c[mt][nt][3] + b1);
                    *(float2*)&g_skip[(size_t)(r + 8) * 64 + jc_in] = o;
                }
            }
        }
    }
}

// ---------------- fused edge conv: warp per dst node ----------------
// For each dst: z_h = sum_e exp(s_eh), out = relu(0.25*sum_h (1/z_h)*sum_e e_eh*v[src] + skip)
__global__ void __launch_bounds__(256, 4) fused_edge(float* __restrict__ out, int N) {
    int node = (blockIdx.x * blockDim.x + threadIdx.x) >> 5;
    int lane = threadIdx.x & 31;
    if (node >= N) return;

    // lane holds q dims lane*8..lane*8+7 (head = lane>>3)
    uint4 q = ((const uint4*)&g_qb[(size_t)node * QK])[lane];
    int beg = g_rowptr[node], end = g_rowptr[node + 1];

    float z = 0.f;
    float acc[8] = {0.f, 0.f, 0.f, 0.f, 0.f, 0.f, 0.f, 0.f};

    for (int i = beg; i < end; i++) {
        int src = g_srcs[i];                         // broadcast load
        uint4 kk = ((const uint4*)&g_kb[(size_t)src * QK])[lane];
        float p = dot2bf(q.x, kk.x) + dot2bf(q.y, kk.y)
                + dot2bf(q.z, kk.z) + dot2bf(q.w, kk.w);
        p += __shfl_xor_sync(0xffffffffu, p, 1);
        p += __shfl_xor_sync(0xffffffffu, p, 2);
        p += __shfl_xor_sync(0xffffffffu, p, 4);     // per-8-lane-group head dot
        float e = __expf(p * 0.125f);                // head of this lane group
        z += e;
        uint4 vv = ((const uint4*)&g_vb[(size_t)src * QK])[lane];
        const uint32_t* uv = (const uint32_t*)&vv;
        #pragma unroll
        for (int j = 0; j < 4; j++) {
            acc[2 * j]     += e * bflo(uv[j]);
            acc[2 * j + 1] += e * bfhi(uv[j]);
        }
    }

    // normalize by this head's z, fold 1/4 head-mean
    float w = (end > beg) ? (0.25f / z) : 0.f;
    #pragma unroll
    for (int j = 0; j < 8; j++) {
        float a = acc[j] * w;
        a += __shfl_xor_sync(0xffffffffu, a, 8);
        a += __shfl_xor_sync(0xffffffffu, a, 16);    // sum over 4 heads
        acc[j] = a;
    }

    if (lane < 8) {
        float* op = &out[(size_t)node * HID + lane * 8];
        const float* sp = &g_skip[(size_t)node * HID + lane * 8];
        float4 s0 = *(const float4*)sp;
        float4 s1 = *(const float4*)(sp + 4);
        float4 o0, o1;
        o0.x = fmaxf(acc[0] + s0.x, 0.f);
        o0.y = fmaxf(acc[1] + s0.y, 0.f);
        o0.z = fmaxf(acc[2] + s0.z, 0.f);
        o0.w = fmaxf(acc[3] + s0.w, 0.f);
        o1.x = fmaxf(acc[4] + s1.x, 0.f);
        o1.y = fmaxf(acc[5] + s1.y, 0.f);
        o1.z = fmaxf(acc[6] + s1.z, 0.f);
        o1.w = fmaxf(acc[7] + s1.w, 0.f);
        *(float4*)op       = o0;
        *(float4*)(op + 4) = o1;
    }
}

// ---------------- pool: per-graph mean of g_h2 (batch is sorted), 64 nodes/block ------
__global__ void pool_kernel(const int* __restrict__ batch, int N) {
    const int NPB = 64;
    int d = threadIdx.x;
    int n0 = blockIdx.x * NPB;
    int n1 = min(n0 + NPB, N);
    float acc = 0.f, cnt = 0.f;
    int cur = -1;
    for (int n = n0; n < n1; n++) {
        int g = batch[n];
        if (g != cur) {
            if (cur >= 0) {
                atomicAdd(&g_gsum[cur * HID + d], acc);
                if (d == 0) atomicAdd(&g_gcnt[cur], cnt);
            }
            cur = g; acc = 0.f; cnt = 0.f;
        }
        acc += g_h2[(size_t)n * HID + d];
        cnt += 1.f;
    }
    if (cur >= 0) {
        atomicAdd(&g_gsum[cur * HID + d], acc);
        if (d == 0) atomicAdd(&g_gcnt[cur], cnt);
    }
}

// ---------------- head: one block per graph ----------------
__global__ void __launch_bounds__(128, 8) head_kernel(
        const float* __restrict__ gf,
        const float* __restrict__ gW1, const float* __restrict__ gb1,
        const float* __restrict__ gW2, const float* __restrict__ gb2,
        const float* __restrict__ hW1, const float* __restrict__ hb1,
        const float* __restrict__ hW2, const float* __restrict__ hb2,
        float* __restrict__ out) {
    __shared__ float s_gf[GDIM];
    __shared__ float s_patch[HID];
    __shared__ float s_g1[HID];
    __shared__ float s_g2[HID];
    __shared__ float s_hid[HID];
    int g = blockIdx.x;
    int t = threadIdx.x;

    for (int i = t; i < GDIM; i += 128) s_gf[i] = gf[g * GDIM + i];
    if (t < HID) s_patch[t] = g_gsum[g * HID + t] / fmaxf(g_gcnt[g], 1.f);
    __syncthreads();

    {
        int j = t >> 1, half = t & 1;
        float s = 0.f;
        int kb = half * 128;
        #pragma unroll 8
        for (int k = 0; k < 128; k++) s += s_gf[kb + k] * gW1[(kb + k) * HID + j];
        s += __shfl_xor_sync(0xffffffffu, s, 1);
        if (half == 0) s_g1[j] = fmaxf(s + gb1[j], 0.f);
    }
    __syncthreads();

    if (t < HID) {
        float s = gb2[t];
        #pragma unroll 8
        for (int k = 0; k < HID; k++) s += s_g1[k] * gW2[k * HID + t];
        s_g2[t] = fmaxf(s, 0.f);
    }
    __syncthreads();

    {
        int j = t >> 1, half = t & 1;
        float s = 0.f;
        const float* src = half ? s_g2 : s_patch;
        int kb = half * HID;
        #pragma unroll 8
        for (int k = 0; k < HID; k++) s += src[k] * hW1[(kb + k) * HID + j];
        s += __shfl_xor_sync(0xffffffffu, s, 1);
        if (half == 0) s_hid[j] = fmaxf(s + hb1[j], 0.f);
    }
    __syncthreads();

    if (t < NCLS) {
        float s = hb2[t];
        #pragma unroll 8
        for (int k = 0; k < HID; k++) s += s_hid[k] * hW2[k * NCLS + t];
        out[g * NCLS + t] = s;
    }
}

// ---------------- host orchestration ----------------
static void run_conv(const float* xin, int K, int N, int E,
                     const float* Wq, const float* bq, const float* Wk, const float* bk,
                     const float* Wv, const float* bv, const float* Ws, const float* bs,
                     float* hout) {
    pack_w<<<(K * OCT + 255) / 256, 256>>>(Wq, bq, Wk, bk, Wv, bv, Ws, bs, K);
    dim3 gg((N + 127) / 128, OCT / 64);
    gemm_qkvs<<<gg, 256>>>(xin, N, K);
    fused_edge<<<(N * 32 + 255) / 256, 256>>>(hout, N);
}

extern "C" void kernel_launch(void* const* d_in, const int* in_sizes, int n_in,
                              void* d_out, int out_size) {
    const float* x     = (const float*)d_in[0];
    const int*   ei    = (const int*)  d_in[1];
    const int*   batch = (const int*)  d_in[2];
    const float* gf    = (const float*)d_in[3];
    const float* c1[8]; for (int i = 0; i < 8; i++) c1[i] = (const float*)d_in[4 + i];
    const float* c2[8]; for (int i = 0; i < 8; i++) c2[i] = (const float*)d_in[12 + i];
    const float* gW1 = (const float*)d_in[20]; const float* gb1 = (const float*)d_in[21];
    const float* gW2 = (const float*)d_in[22]; const float* gb2 = (const float*)d_in[23];
    const float* hW1 = (const float*)d_in[24]; const float* hb1 = (const float*)d_in[25];
    const float* hW2 = (const float*)d_in[26]; const float* hb2 = (const float*)d_in[27];

    int N = in_sizes[0] / 128;
    int E = in_sizes[1] / 2;

    void *p_h1, *p_h2, *p_gsum, *p_gcnt, *p_cursor;
    cudaGetSymbolAddress(&p_h1,     g_h1);
    cudaGetSymbolAddress(&p_h2,     g_h2);
    cudaGetSymbolAddress(&p_gsum,   g_gsum);
    cudaGetSymbolAddress(&p_gcnt,   g_gcnt);
    cudaGetSymbolAddress(&p_cursor, g_cursor);

    // ---- build CSR once (reused by both convs) ----
    cudaMemsetAsync(p_cursor, 0, (size_t)N * sizeof(int), 0);
    hist_kernel<<<(E + 255) / 256, 256>>>(ei, E);
    scan_kernel<<<1, 1024>>>(N, E);
    scatter_kernel<<<(E + 255) / 256, 256>>>(ei, E);

    // conv1 (in=128)
    run_conv(x, 128, N, E,
             c1[0], c1[1], c1[2], c1[3], c1[4], c1[5], c1[6], c1[7], (float*)p_h1);
    // conv2 (in=64)
    run_conv((const float*)p_h1, 64, N, E,
             c2[0], c2[1], c2[2], c2[3], c2[4], c2[5], c2[6], c2[7], (float*)p_h2);

    // pooling
    cudaMemsetAsync(p_gsum, 0, NGRAPH * HID * sizeof(float), 0);
    cudaMemsetAsync(p_gcnt, 0, NGRAPH * sizeof(float), 0);
    pool_kernel<<<(N + 63) / 64, HID>>>(batch, N);

    // head (one block per graph)
    head_kernel<<<NGRAPH, 128>>>(gf, gW1, gb1, gW2, gb2, hW1, hb1, hW2, hb2, (float*)d_out);
}

// round 11
// speedup vs baseline: 2.5320x; 1.2642x over previous
#include <cuda_runtime.h>
#include <cuda_bf16.h>
#include <math.h>
#include <cstdint>

// Problem constants
#define NMAX   50000
#define EMAX   800000
#define HEADS  4
#define HID    64
#define QK     256        // HEADS*HID
#define OCT    832        // 3*QK + HID
#define NGRAPH 64
#define GDIM   256
#define NCLS   10

// ---------------- scratch (device globals; no runtime allocation) ----------------
__device__ __align__(16) __nv_bfloat16 g_qb[NMAX * QK];   // bf16 q
__device__ __align__(16) __nv_bfloat16 g_kb[NMAX * QK];   // bf16 k
__device__ __align__(16) __nv_bfloat16 g_vb[NMAX * QK];   // bf16 v
__device__ __align__(16) float    g_skip[NMAX * HID];
__device__ __align__(16) float    g_h1  [NMAX * HID];
__device__ __align__(16) float    g_h2  [NMAX * HID];
__device__ __align__(16) float    g_Wc  [128 * OCT];
__device__ __align__(16) float    g_bc  [OCT];
__device__ __align__(16) float    g_gsum[NGRAPH * HID];
__device__ __align__(16) float    g_gcnt[NGRAPH];
// CSR (dst-sorted) graph, built once per launch
__device__ __align__(16) int      g_rowptr[NMAX + 1];
__device__ __align__(16) int      g_cursor[NMAX];
__device__ __align__(16) int      g_srcs  [EMAX];

// ---------------- helpers ----------------
__device__ __forceinline__ uint32_t pack_bf16(float a, float b) {
    __nv_bfloat16 ha = __float2bfloat16_rn(a);
    __nv_bfloat16 hb = __float2bfloat16_rn(b);
    return (uint32_t)__bfloat16_as_ushort(ha) | ((uint32_t)__bfloat16_as_ushort(hb) << 16);
}
__device__ __forceinline__ float bf_hi_res(float v) {   // v - bf16(v)
    return v - __bfloat162float(__float2bfloat16_rn(v));
}
__device__ __forceinline__ float bflo(uint32_t u) { return __uint_as_float(u << 16); }
__device__ __forceinline__ float bfhi(uint32_t u) { return __uint_as_float(u & 0xffff0000u); }
__device__ __forceinline__ float dot2bf(uint32_t ua, uint32_t ub) {
    return bflo(ua) * bflo(ub) + bfhi(ua) * bfhi(ub);
}

#define MMA_BF16(c, a, b)                                                     \
    asm volatile("mma.sync.aligned.m16n8k16.row.col.f32.bf16.bf16.f32 "       \
                 "{%0,%1,%2,%3}, {%4,%5,%6,%7}, {%8,%9}, {%0,%1,%2,%3};"      \
                 : "+f"((c)[0]), "+f"((c)[1]), "+f"((c)[2]), "+f"((c)[3])     \
                 : "r"((a)[0]), "r"((a)[1]), "r"((a)[2]), "r"((a)[3]),        \
                   "r"((b)[0]), "r"((b)[1]))

// ---------------- CSR build ----------------
__global__ void hist_kernel(const int* __restrict__ ei, int E) {
    int e = blockIdx.x * blockDim.x + threadIdx.x;
    if (e < E) atomicAdd(&g_cursor[ei[E + e]], 1);
}
__global__ void scan_kernel(int N, int E) {
    __shared__ int s_part[1024];
    int t = threadIdx.x;
    int chunk = (N + 1023) >> 10;
    int b = t * chunk, en = min(b + chunk, N);
    int sum = 0;
    for (int i = b; i < en; i++) sum += g_cursor[i];
    s_part[t] = sum;
    __syncthreads();
    for (int off = 1; off < 1024; off <<= 1) {
        int v = (t >= off) ? s_part[t - off] : 0;
        __syncthreads();
        s_part[t] += v;
        __syncthreads();
    }
    int run = s_part[t] - sum;   // exclusive base
    for (int i = b; i < en; i++) {
        int c = g_cursor[i];
        g_rowptr[i] = run;
        g_cursor[i] = run;
        run += c;
    }
    if (t == 0) g_rowptr[N] = E;
}
__global__ void scatter_kernel(const int* __restrict__ ei, int E) {
    int e = blockIdx.x * blockDim.x + threadIdx.x;
    if (e >= E) return;
    int src = ei[e], dst = ei[E + e];
    int pos = atomicAdd(&g_cursor[dst], 1);
    g_srcs[pos] = src;
}

// ---------------- weight pack ----------------
__global__ void pack_w(const float* __restrict__ Wq, const float* __restrict__ bq,
                       const float* __restrict__ Wk, const float* __restrict__ bk,
                       const float* __restrict__ Wv, const float* __restrict__ bv,
                       const float* __restrict__ Ws, const float* __restrict__ bs, int K) {
    int idx = blockIdx.x * blockDim.x + threadIdx.x;
    int tot = K * OCT;
    if (idx < tot) {
        int k = idx / OCT, j = idx - k * OCT;
        float v;
        if      (j < 256) v = Wq[k * 256 + j];
        else if (j < 512) v = Wk[k * 256 + (j - 256)];
        else if (j < 768) v = Wv[k * 256 + (j - 512)];
        else              v = Ws[k * 64  + (j - 768)];
        g_Wc[idx] = v;
    }
    if (idx < OCT) {
        float b;
        if      (idx < 256) b = bq[idx];
        else if (idx < 512) b = bk[idx - 256];
        else if (idx < 768) b = bv[idx - 512];
        else                b = bs[idx - 768];
        g_bc[idx] = b;
    }
}

// ---------------- GEMM: 2-term bf16 mma.sync.m16n8k16 (A bf16, B hi/lo split) --------
// Data-side (A) rounding is per-node independent and pools away; weight-side (B)
// rounding is systematic across nodes, so B keeps the exact hi/lo split.
#define ASTR32 136
#define BSTR32 72
__global__ void __launch_bounds__(256, 2) gemm_qkvs(const float* __restrict__ A, int N, int K) {
    __shared__ uint32_t As[8 * ASTR32];      // [kpair][m], A bf16 single
    __shared__ uint32_t Bs[2][8 * BSTR32];   // [hi/lo][kpair][n]
    const int t    = threadIdx.x;
    const int lane = t & 31, wid = t >> 5;
    const int warp_m = wid & 3;
    const int warp_n = wid >> 2;
    const int row0 = blockIdx.x * 128, col0 = blockIdx.y * 64;
    const int lq = lane >> 2;
    const int lr = lane & 3;

    float c[2][4][4];
    #pragma unroll
    for (int mt = 0; mt < 2; mt++)
        #pragma unroll
        for (int nt = 0; nt < 4; nt++)
            #pragma unroll
            for (int i = 0; i < 4; i++) c[mt][nt][i] = 0.f;

    for (int k0 = 0; k0 < K; k0 += 16) {
        #pragma unroll
        for (int ii = 0; ii < 2; ii++) {
            int idx = t + ii * 256;
            int r = idx >> 2, cg = (idx & 3) << 2;
            int gr = row0 + r;
            float4 a = (gr < N) ? *(const float4*)&A[(size_t)gr * K + k0 + cg]
                                : make_float4(0.f, 0.f, 0.f, 0.f);
            int kp = cg >> 1;
            As[kp * ASTR32 + r]       = pack_bf16(a.x, a.y);
            As[(kp + 1) * ASTR32 + r] = pack_bf16(a.z, a.w);
        }
        if (t < 128) {
            int kp = t >> 4, j4 = (t & 15) << 2;
            const float* r0p = &g_Wc[(size_t)(k0 + 2 * kp) * OCT + col0 + j4];
            const float* r1p = r0p + OCT;
            float4 b0 = *(const float4*)r0p;
            float4 b1 = *(const float4*)r1p;
            float v0[4] = {b0.x, b0.y, b0.z, b0.w};
            float v1[4] = {b1.x, b1.y, b1.z, b1.w};
            #pragma unroll
            for (int i = 0; i < 4; i++) {
                Bs[0][kp * BSTR32 + j4 + i] = pack_bf16(v0[i], v1[i]);
                Bs[1][kp * BSTR32 + j4 + i] = pack_bf16(bf_hi_res(v0[i]), bf_hi_res(v1[i]));
            }
        }
        __syncthreads();

        uint32_t ah[2][4];
        #pragma unroll
        for (int mt = 0; mt < 2; mt++) {
            int r0 = warp_m * 32 + mt * 16 + lq;
            ah[mt][0] = As[lr * ASTR32 + r0];
            ah[mt][1] = As[lr * ASTR32 + r0 + 8];
            ah[mt][2] = As[(lr + 4) * ASTR32 + r0];
            ah[mt][3] = As[(lr + 4) * ASTR32 + r0 + 8];
        }
        uint32_t bh[4][2], bl[4][2];
        #pragma unroll
        for (int nt = 0; nt < 4; nt++) {
            int n = warp_n * 32 + nt * 8 + lq;
            bh[nt][0] = Bs[0][lr * BSTR32 + n];
            bh[nt][1] = Bs[0][(lr + 4) * BSTR32 + n];
            bl[nt][0] = Bs[1][lr * BSTR32 + n];
            bl[nt][1] = Bs[1][(lr + 4) * BSTR32 + n];
        }
        #pragma unroll
        for (int mt = 0; mt < 2; mt++)
            #pragma unroll
            for (int nt = 0; nt < 4; nt++) {
                MMA_BF16(c[mt][nt], ah[mt], bh[nt]);
                MMA_BF16(c[mt][nt], ah[mt], bl[nt]);
            }
        __syncthreads();
    }

    int y = blockIdx.y;
    bool is_bf = (y < 12);
    __nv_bfloat16* bfdst; int bfoff;
    if      (y < 4) { bfdst = g_qb; bfoff = col0;       }
    else if (y < 8) { bfdst = g_kb; bfoff = col0 - 256; }
    else            { bfdst = g_vb; bfoff = col0 - 512; }

    #pragma unroll
    for (int mt = 0; mt < 2; mt++) {
        int r = row0 + warp_m * 32 + mt * 16 + lq;
        #pragma unroll
        for (int nt = 0; nt < 4; nt++) {
            int jc_in = warp_n * 32 + nt * 8 + lr * 2;
            float b0 = g_bc[col0 + jc_in];
            float b1 = g_bc[col0 + jc_in + 1];
            if (is_bf) {
                if (r < N) {
                    *(uint32_t*)&bfdst[(size_t)r * 256 + bfoff + jc_in] =
                        pack_bf16(c[mt][nt][0] + b0, c[mt][nt][1] + b1);
                }
                if (r + 8 < N) {
                    *(uint32_t*)&bfdst[(size_t)(r + 8) * 256 + bfoff + jc_in] =
                        pack_bf16(c[mt][nt][2] + b0, c[mt][nt][3] + b1);
                }
            } else {
                if (r < N) {
                    float2 o = make_float2(c[mt][nt][0] + b0, c[mt][nt][1] + b1);
                    *(float2*)&g_skip[(size_t)r * 64 + jc_in] = o;
                }
                if (r + 8 < N) {
                    float2 o = make_float2(c[mt][nt][2] + b0, c[mt][nt][3] + b1);
                    *(float2*)&g_skip[(size_t)(r + 8) * 64 + jc_in] = o;
                }
            }
        }
    }
}

// ---------------- fused edge conv: warp per dst node, 2-edge unrolled ----------------
__global__ void __launch_bounds__(256, 4) fused_edge(float* __restrict__ out, int N) {
    int node = (blockIdx.x * blockDim.x + threadIdx.x) >> 5;
    int lane = threadIdx.x & 31;
    if (node >= N) return;

    uint4 q = ((const uint4*)&g_qb[(size_t)node * QK])[lane];
    int beg = g_rowptr[node], end = g_rowptr[node + 1];

    float z = 0.f;
    float acc[8] = {0.f, 0.f, 0.f, 0.f, 0.f, 0.f, 0.f, 0.f};

    int i = beg;
    for (; i + 2 <= end; i += 2) {
        int s0 = g_srcs[i], s1 = g_srcs[i + 1];
        uint4 k0 = ((const uint4*)&g_kb[(size_t)s0 * QK])[lane];
        uint4 k1 = ((const uint4*)&g_kb[(size_t)s1 * QK])[lane];
        uint4 v0 = ((const uint4*)&g_vb[(size_t)s0 * QK])[lane];
        uint4 v1 = ((const uint4*)&g_vb[(size_t)s1 * QK])[lane];
        float p0 = dot2bf(q.x, k0.x) + dot2bf(q.y, k0.y) + dot2bf(q.z, k0.z) + dot2bf(q.w, k0.w);
        float p1 = dot2bf(q.x, k1.x) + dot2bf(q.y, k1.y) + dot2bf(q.z, k1.z) + dot2bf(q.w, k1.w);
        p0 += __shfl_xor_sync(0xffffffffu, p0, 1);
        p1 += __shfl_xor_sync(0xffffffffu, p1, 1);
        p0 += __shfl_xor_sync(0xffffffffu, p0, 2);
        p1 += __shfl_xor_sync(0xffffffffu, p1, 2);
        p0 += __shfl_xor_sync(0xffffffffu, p0, 4);
        p1 += __shfl_xor_sync(0xffffffffu, p1, 4);
        float e0 = __expf(p0 * 0.125f);
        float e1 = __expf(p1 * 0.125f);
        z += e0 + e1;
        const uint32_t* u0 = (const uint32_t*)&v0;
        const uint32_t* u1 = (const uint32_t*)&v1;
        #pragma unroll
        for (int j = 0; j < 4; j++) {
            acc[2 * j]     += e0 * bflo(u0[j]) + e1 * bflo(u1[j]);
            acc[2 * j + 1] += e0 * bfhi(u0[j]) + e1 * bfhi(u1[j]);
        }
    }
    if (i < end) {
        int s0 = g_srcs[i];
        uint4 k0 = ((const uint4*)&g_kb[(size_t)s0 * QK])[lane];
        uint4 v0 = ((const uint4*)&g_vb[(size_t)s0 * QK])[lane];
        float p0 = dot2bf(q.x, k0.x) + dot2bf(q.y, k0.y) + dot2bf(q.z, k0.z) + dot2bf(q.w, k0.w);
        p0 += __shfl_xor_sync(0xffffffffu, p0, 1);
        p0 += __shfl_xor_sync(0xffffffffu, p0, 2);
        p0 += __shfl_xor_sync(0xffffffffu, p0, 4);
        float e0 = __expf(p0 * 0.125f);
        z += e0;
        const uint32_t* u0 = (const uint32_t*)&v0;
        #pragma unroll
        for (int j = 0; j < 4; j++) {
            acc[2 * j]     += e0 * bflo(u0[j]);
            acc[2 * j + 1] += e0 * bfhi(u0[j]);
        }
    }

    float w = (end > beg) ? (0.25f / z) : 0.f;
    #pragma unroll
    for (int j = 0; j < 8; j++) {
        float a = acc[j] * w;
        a += __shfl_xor_sync(0xffffffffu, a, 8);
        a += __shfl_xor_sync(0xffffffffu, a, 16);
        acc[j] = a;
    }

    if (lane < 8) {
        float* op = &out[(size_t)node * HID + lane * 8];
        const float* sp = &g_skip[(size_t)node * HID + lane * 8];
        float4 s0 = *(const float4*)sp;
        float4 s1 = *(const float4*)(sp + 4);
        float4 o0, o1;
        o0.x = fmaxf(acc[0] + s0.x, 0.f);
        o0.y = fmaxf(acc[1] + s0.y, 0.f);
        o0.z = fmaxf(acc[2] + s0.z, 0.f);
        o0.w = fmaxf(acc[3] + s0.w, 0.f);
        o1.x = fmaxf(acc[4] + s1.x, 0.f);
        o1.y = fmaxf(acc[5] + s1.y, 0.f);
        o1.z = fmaxf(acc[6] + s1.z, 0.f);
        o1.w = fmaxf(acc[7] + s1.w, 0.f);
        *(float4*)op       = o0;
        *(float4*)(op + 4) = o1;
    }
}

// ---------------- pool: per-graph mean of g_h2 (batch is sorted), 64 nodes/block ------
__global__ void pool_kernel(const int* __restrict__ batch, int N) {
    const int NPB = 64;
    int d = threadIdx.x;
    int n0 = blockIdx.x * NPB;
    int n1 = min(n0 + NPB, N);
    float acc = 0.f, cnt = 0.f;
    int cur = -1;
    for (int n = n0; n < n1; n++) {
        int g = batch[n];
        if (g != cur) {
            if (cur >= 0) {
                atomicAdd(&g_gsum[cur * HID + d], acc);
                if (d == 0) atomicAdd(&g_gcnt[cur], cnt);
            }
            cur = g; acc = 0.f; cnt = 0.f;
        }
        acc += g_h2[(size_t)n * HID + d];
        cnt += 1.f;
    }
    if (cur >= 0) {
        atomicAdd(&g_gsum[cur * HID + d], acc);
        if (d == 0) atomicAdd(&g_gcnt[cur], cnt);
    }
}

// ---------------- head: one block per graph ----------------
__global__ void __launch_bounds__(128, 8) head_kernel(
        const float* __restrict__ gf,
        const float* __restrict__ gW1, const float* __restrict__ gb1,
        const float* __restrict__ gW2, const float* __restrict__ gb2,
        const float* __restrict__ hW1, const float* __restrict__ hb1,
        const float* __restrict__ hW2, const float* __restrict__ hb2,
        float* __restrict__ out) {
    __shared__ float s_gf[GDIM];
    __shared__ float s_patch[HID];
    __shared__ float s_g1[HID];
    __shared__ float s_g2[HID];
    __shared__ float s_hid[HID];
    int g = blockIdx.x;
    int t = threadIdx.x;

    for (int i = t; i < GDIM; i += 128) s_gf[i] = gf[g * GDIM + i];
    if (t < HID) s_patch[t] = g_gsum[g * HID + t] / fmaxf(g_gcnt[g], 1.f);
    __syncthreads();

    {
        int j = t >> 1, half = t & 1;
        float s = 0.f;
        int kb = half * 128;
        #pragma unroll 8
        for (int k = 0; k < 128; k++) s += s_gf[kb + k] * gW1[(kb + k) * HID + j];
        s += __shfl_xor_sync(0xffffffffu, s, 1);
        if (half == 0) s_g1[j] = fmaxf(s + gb1[j], 0.f);
    }
    __syncthreads();

    if (t < HID) {
        float s = gb2[t];
        #pragma unroll 8
        for (int k = 0; k < HID; k++) s += s_g1[k] * gW2[k * HID + t];
        s_g2[t] = fmaxf(s, 0.f);
    }
    __syncthreads();

    {
        int j = t >> 1, half = t & 1;
        float s = 0.f;
        const float* src = half ? s_g2 : s_patch;
        int kb = half * HID;
        #pragma unroll 8
        for (int k = 0; k < HID; k++) s += src[k] * hW1[(kb + k) * HID + j];
        s += __shfl_xor_sync(0xffffffffu, s, 1);
        if (half == 0) s_hid[j] = fmaxf(s + hb1[j], 0.f);
    }
    __syncthreads();

    if (t < NCLS) {
        float s = hb2[t];
        #pragma unroll 8
        for (int k = 0; k < HID; k++) s += s_hid[k] * hW2[k * NCLS + t];
        out[g * NCLS + t] = s;
    }
}

// ---------------- host orchestration ----------------
static void run_conv(const float* xin, int K, int N, int E,
                     const float* Wq, const float* bq, const float* Wk, const float* bk,
                     const float* Wv, const float* bv, const float* Ws, const float* bs,
                     float* hout) {
    pack_w<<<(K * OCT + 255) / 256, 256>>>(Wq, bq, Wk, bk, Wv, bv, Ws, bs, K);
    dim3 gg((N + 127) / 128, OCT / 64);
    gemm_qkvs<<<gg, 256>>>(xin, N, K);
    fused_edge<<<(N * 32 + 255) / 256, 256>>>(hout, N);
}

extern "C" void kernel_launch(void* const* d_in, const int* in_sizes, int n_in,
                              void* d_out, int out_size) {
    const float* x     = (const float*)d_in[0];
    const int*   ei    = (const int*)  d_in[1];
    const int*   batch = (const int*)  d_in[2];
    const float* gf    = (const float*)d_in[3];
    const float* c1[8]; for (int i = 0; i < 8; i++) c1[i] = (const float*)d_in[4 + i];
    const float* c2[8]; for (int i = 0; i < 8; i++) c2[i] = (const float*)d_in[12 + i];
    const float* gW1 = (const float*)d_in[20]; const float* gb1 = (const float*)d_in[21];
    const float* gW2 = (const float*)d_in[22]; const float* gb2 = (const float*)d_in[23];
    const float* hW1 = (const float*)d_in[24]; const float* hb1 = (const float*)d_in[25];
    const float* hW2 = (const float*)d_in[26]; const float* hb2 = (const float*)d_in[27];

    int N = in_sizes[0] / 128;
    int E = in_sizes[1] / 2;

    void *p_h1, *p_h2, *p_gsum, *p_gcnt, *p_cursor;
    cudaGetSymbolAddress(&p_h1,     g_h1);
    cudaGetSymbolAddress(&p_h2,     g_h2);
    cudaGetSymbolAddress(&p_gsum,   g_gsum);
    cudaGetSymbolAddress(&p_gcnt,   g_gcnt);
    cudaGetSymbolAddress(&p_cursor, g_cursor);

    // ---- build CSR once (reused by both convs) ----
    cudaMemsetAsync(p_cursor, 0, (size_t)N * sizeof(int), 0);
    hist_kernel<<<(E + 255) / 256, 256>>>(ei, E);
    scan_kernel<<<1, 1024>>>(N, E);
    scatter_kernel<<<(E + 255) / 256, 256>>>(ei, E);

    // conv1 (in=128)
    run_conv(x, 128, N, E,
             c1[0], c1[1], c1[2], c1[3], c1[4], c1[5], c1[6], c1[7], (float*)p_h1);
    // conv2 (in=64)
    run_conv((const float*)p_h1, 64, N, E,
             c2[0], c2[1], c2[2], c2[3], c2[4], c2[5], c2[6], c2[7], (float*)p_h2);

    // pooling
    cudaMemsetAsync(p_gsum, 0, NGRAPH * HID * sizeof(float), 0);
    cudaMemsetAsync(p_gcnt, 0, NGRAPH * sizeof(float), 0);
    pool_kernel<<<(N + 63) / 64, HID>>>(batch, N);

    // head (one block per graph)
    head_kernel<<<NGRAPH, 128>>>(gf, gW1, gb1, gW2, gb2, hW1, hb1, hW2, hb2, (float*)d_out);
}